// round 1
// baseline (speedup 1.0000x reference)
#include <cuda_runtime.h>

#define BATCH 2
#define HEADS 16
#define SEQ   2048
#define DIM   1024
#define HD    64
#define QKV_N (3*DIM)
#define MROWS (BATCH*SEQ)   // 4096

// Scratch (no allocations allowed): 4 x 16MB
__device__ float g_Q[BATCH*HEADS*SEQ*HD];
__device__ float g_K[BATCH*HEADS*SEQ*HD];
__device__ float g_V[BATCH*HEADS*SEQ*HD];
__device__ float g_attn[BATCH*SEQ*DIM];

// ---------------------------------------------------------------------------
// GEMM 1: qkv = x @ w_qkv + b_qkv, scattered to [B,H,N,hd] Q/K/V tensors.
// A: [4096,1024] row-major, W: [1024,3072] row-major.
// BM=BN=128, BK=16, 256 threads, 8x8 per-thread microtile.
// ---------------------------------------------------------------------------
__global__ __launch_bounds__(256) void gemm_qkv(const float* __restrict__ A,
                                                const float* __restrict__ W,
                                                const float* __restrict__ bias)
{
    const int K = DIM, Nc = QKV_N;
    __shared__ float As[16][128];
    __shared__ float Bs[16][128];

    const int tid = threadIdx.x;
    const int ty = tid >> 4, tx = tid & 15;
    const int row0 = blockIdx.y * 128, col0 = blockIdx.x * 128;

    float acc[8][8];
#pragma unroll
    for (int i = 0; i < 8; i++)
#pragma unroll
        for (int j = 0; j < 8; j++) acc[i][j] = 0.f;

    for (int k0 = 0; k0 < K; k0 += 16) {
        // A tile: 128 rows x 16 cols = 512 float4
#pragma unroll
        for (int i = 0; i < 2; i++) {
            int f = tid * 2 + i;
            int ar = f >> 2, ac = (f & 3) * 4;
            float4 v = *(const float4*)&A[(size_t)(row0 + ar) * K + k0 + ac];
            As[ac + 0][ar] = v.x; As[ac + 1][ar] = v.y;
            As[ac + 2][ar] = v.z; As[ac + 3][ar] = v.w;
        }
        // B tile: 16 rows x 128 cols = 512 float4
#pragma unroll
        for (int i = 0; i < 2; i++) {
            int f = tid * 2 + i;
            int br = f >> 5, bc = (f & 31) * 4;
            *(float4*)&Bs[br][bc] =
                *(const float4*)&W[(size_t)(k0 + br) * Nc + col0 + bc];
        }
        __syncthreads();

#pragma unroll
        for (int kk = 0; kk < 16; kk++) {
            float a[8], b[8];
#pragma unroll
            for (int i = 0; i < 8; i++) a[i] = As[kk][ty * 8 + i];
#pragma unroll
            for (int j = 0; j < 8; j++) b[j] = Bs[kk][tx * 8 + j];
#pragma unroll
            for (int i = 0; i < 8; i++)
#pragma unroll
                for (int j = 0; j < 8; j++) acc[i][j] += a[i] * b[j];
        }
        __syncthreads();
    }

    // Epilogue: bias + scatter into [B,H,N,hd].
#pragma unroll
    for (int i = 0; i < 8; i++) {
        int r = row0 + ty * 8 + i;
        int b_ = r >> 11, n = r & (SEQ - 1);
#pragma unroll
        for (int j = 0; j < 8; j++) {
            int c = col0 + tx * 8 + j;
            float val = acc[i][j] + bias[c];
            int s = c >> 10;           // 0=Q 1=K 2=V
            int rr = c & (DIM - 1);
            int h = rr >> 6, d = rr & (HD - 1);
            float* dst = (s == 0) ? g_Q : (s == 1) ? g_K : g_V;
            dst[(((size_t)(b_ * HEADS + h) * SEQ) + n) * HD + d] = val;
        }
    }
}

// ---------------------------------------------------------------------------
// Flash-style attention. Block: 64 queries of one (b,h); 256 threads.
// Each query row owned by 4 threads (tid&3): each holds 16 output dims.
// Key tiles of 32. smem ~42KB (static, under 48KB default).
// ---------------------------------------------------------------------------
__global__ __launch_bounds__(256) void attn_kernel()
{
    __shared__ float Qs[64][65];
    __shared__ float Ks[32][65];
    __shared__ float Vs[32][65];
    __shared__ float Ss[64][33];

    const int tid = threadIdx.x;
    const int bh = blockIdx.y;                 // b*HEADS + h
    const int q0 = blockIdx.x * 64;
    const int q = tid >> 2;
    const int dsl = (tid & 3) * 16;            // 16-dim slice of output
    const int ksl = (tid & 3) * 8;             // 8-key slice for scores

    // Load Q tile, pre-scaled by 1/sqrt(hd)=0.125
    const float* Qg = g_Q + ((size_t)bh * SEQ + q0) * HD;
    for (int idx = tid; idx < 64 * 16; idx += 256) {
        int r = idx >> 4, c4 = (idx & 15) * 4;
        float4 v = *(const float4*)&Qg[r * HD + c4];
        Qs[r][c4 + 0] = v.x * 0.125f; Qs[r][c4 + 1] = v.y * 0.125f;
        Qs[r][c4 + 2] = v.z * 0.125f; Qs[r][c4 + 3] = v.w * 0.125f;
    }

    float m_i = -1e30f, l_i = 0.f;
    float out[16];
#pragma unroll
    for (int d = 0; d < 16; d++) out[d] = 0.f;

    for (int kt = 0; kt < SEQ; kt += 32) {
        const float* Kg = g_K + ((size_t)bh * SEQ + kt) * HD;
        const float* Vg = g_V + ((size_t)bh * SEQ + kt) * HD;
        __syncthreads();
        for (int idx = tid; idx < 32 * 16; idx += 256) {
            int r = idx >> 4, c4 = (idx & 15) * 4;
            float4 kv = *(const float4*)&Kg[r * HD + c4];
            Ks[r][c4 + 0] = kv.x; Ks[r][c4 + 1] = kv.y;
            Ks[r][c4 + 2] = kv.z; Ks[r][c4 + 3] = kv.w;
            float4 vv = *(const float4*)&Vg[r * HD + c4];
            Vs[r][c4 + 0] = vv.x; Vs[r][c4 + 1] = vv.y;
            Vs[r][c4 + 2] = vv.z; Vs[r][c4 + 3] = vv.w;
        }
        __syncthreads();

        // Scores: each thread does 8 keys x 64-dot
#pragma unroll
        for (int k = 0; k < 8; k++) {
            float s = 0.f;
#pragma unroll
            for (int x = 0; x < 64; x++) s += Qs[q][x] * Ks[ksl + k][x];
            Ss[q][ksl + k] = s;
        }
        __syncthreads();

        // Online softmax update (each of the 4 row-threads reads full row)
        float mt = m_i;
#pragma unroll
        for (int k = 0; k < 32; k++) mt = fmaxf(mt, Ss[q][k]);
        float corr = __expf(m_i - mt);
        m_i = mt;
        l_i *= corr;
#pragma unroll
        for (int d = 0; d < 16; d++) out[d] *= corr;
#pragma unroll
        for (int k = 0; k < 32; k++) {
            float p = __expf(Ss[q][k] - m_i);
            l_i += p;
#pragma unroll
            for (int d = 0; d < 16; d++) out[d] += p * Vs[k][dsl + d];
        }
    }

    // Write to [B,N,D] scratch for the output projection
    const int b_ = bh >> 4, h = bh & 15;
    const float inv = 1.f / l_i;
    float* og = g_attn + ((size_t)(b_ * SEQ + q0 + q)) * DIM + h * HD + dsl;
#pragma unroll
    for (int d = 0; d < 16; d++) og[d] = out[d] * inv;
}

// ---------------------------------------------------------------------------
// GEMM 2: out = attn @ w_out + b_out  ([4096,1024] x [1024,1024])
// ---------------------------------------------------------------------------
__global__ __launch_bounds__(256) void gemm_out(const float* __restrict__ W,
                                                const float* __restrict__ bias,
                                                float* __restrict__ out)
{
    const int K = DIM, Nc = DIM;
    const float* A = g_attn;
    __shared__ float As[16][128];
    __shared__ float Bs[16][128];

    const int tid = threadIdx.x;
    const int ty = tid >> 4, tx = tid & 15;
    const int row0 = blockIdx.y * 128, col0 = blockIdx.x * 128;

    float acc[8][8];
#pragma unroll
    for (int i = 0; i < 8; i++)
#pragma unroll
        for (int j = 0; j < 8; j++) acc[i][j] = 0.f;

    for (int k0 = 0; k0 < K; k0 += 16) {
#pragma unroll
        for (int i = 0; i < 2; i++) {
            int f = tid * 2 + i;
            int ar = f >> 2, ac = (f & 3) * 4;
            float4 v = *(const float4*)&A[(size_t)(row0 + ar) * K + k0 + ac];
            As[ac + 0][ar] = v.x; As[ac + 1][ar] = v.y;
            As[ac + 2][ar] = v.z; As[ac + 3][ar] = v.w;
        }
#pragma unroll
        for (int i = 0; i < 2; i++) {
            int f = tid * 2 + i;
            int br = f >> 5, bc = (f & 31) * 4;
            *(float4*)&Bs[br][bc] =
                *(const float4*)&W[(size_t)(k0 + br) * Nc + col0 + bc];
        }
        __syncthreads();

#pragma unroll
        for (int kk = 0; kk < 16; kk++) {
            float a[8], b[8];
#pragma unroll
            for (int i = 0; i < 8; i++) a[i] = As[kk][ty * 8 + i];
#pragma unroll
            for (int j = 0; j < 8; j++) b[j] = Bs[kk][tx * 8 + j];
#pragma unroll
            for (int i = 0; i < 8; i++)
#pragma unroll
                for (int j = 0; j < 8; j++) acc[i][j] += a[i] * b[j];
        }
        __syncthreads();
    }

#pragma unroll
    for (int i = 0; i < 8; i++) {
        int r = row0 + ty * 8 + i;
#pragma unroll
        for (int j = 0; j < 8; j += 4) {
            int c = col0 + tx * 8 + j;
            float4 v;
            v.x = acc[i][j + 0] + bias[c + 0];
            v.y = acc[i][j + 1] + bias[c + 1];
            v.z = acc[i][j + 2] + bias[c + 2];
            v.w = acc[i][j + 3] + bias[c + 3];
            *(float4*)&out[(size_t)r * Nc + c] = v;
        }
    }
}

extern "C" void kernel_launch(void* const* d_in, const int* in_sizes, int n_in,
                              void* d_out, int out_size)
{
    (void)in_sizes; (void)n_in; (void)out_size;
    const float* x     = (const float*)d_in[0];
    const float* w_qkv = (const float*)d_in[1];
    const float* b_qkv = (const float*)d_in[2];
    const float* w_out = (const float*)d_in[3];
    const float* b_out = (const float*)d_in[4];
    float* out = (float*)d_out;

    gemm_qkv<<<dim3(QKV_N / 128, MROWS / 128), 256>>>(x, w_qkv, b_qkv);
    attn_kernel<<<dim3(SEQ / 64, BATCH * HEADS), 256>>>();
    gemm_out<<<dim3(DIM / 128, MROWS / 128), 256>>>(w_out, b_out, out);
}

// round 3
// speedup vs baseline: 1.2494x; 1.2494x over previous
#include <cuda_runtime.h>

#define BATCH 2
#define HEADS 16
#define SEQ   2048
#define DIM   1024
#define HD    64
#define QKV_N (3*DIM)
#define MROWS (BATCH*SEQ)   // 4096

// Scratch (no allocations allowed)
__device__ float g_Q[BATCH*HEADS*SEQ*HD];
__device__ float g_K[BATCH*HEADS*SEQ*HD];
__device__ float g_V[BATCH*HEADS*SEQ*HD];
__device__ float g_attn[BATCH*SEQ*DIM];

// ---------------------------------------------------------------------------
// GEMM 1: qkv = x @ w_qkv + b_qkv, scattered to [B,H,N,hd] Q/K/V tensors.
// ---------------------------------------------------------------------------
__global__ __launch_bounds__(256) void gemm_qkv(const float* __restrict__ A,
                                                const float* __restrict__ W,
                                                const float* __restrict__ bias)
{
    const int K = DIM, Nc = QKV_N;
    __shared__ float As[16][128];
    __shared__ float Bs[16][128];

    const int tid = threadIdx.x;
    const int ty = tid >> 4, tx = tid & 15;
    const int row0 = blockIdx.y * 128, col0 = blockIdx.x * 128;

    float acc[8][8];
#pragma unroll
    for (int i = 0; i < 8; i++)
#pragma unroll
        for (int j = 0; j < 8; j++) acc[i][j] = 0.f;

    for (int k0 = 0; k0 < K; k0 += 16) {
#pragma unroll
        for (int i = 0; i < 2; i++) {
            int f = tid * 2 + i;
            int ar = f >> 2, ac = (f & 3) * 4;
            float4 v = *(const float4*)&A[(size_t)(row0 + ar) * K + k0 + ac];
            As[ac + 0][ar] = v.x; As[ac + 1][ar] = v.y;
            As[ac + 2][ar] = v.z; As[ac + 3][ar] = v.w;
        }
#pragma unroll
        for (int i = 0; i < 2; i++) {
            int f = tid * 2 + i;
            int br = f >> 5, bc = (f & 31) * 4;
            *(float4*)&Bs[br][bc] =
                *(const float4*)&W[(size_t)(k0 + br) * Nc + col0 + bc];
        }
        __syncthreads();

#pragma unroll
        for (int kk = 0; kk < 16; kk++) {
            float a[8], b[8];
#pragma unroll
            for (int i = 0; i < 8; i++) a[i] = As[kk][ty * 8 + i];
#pragma unroll
            for (int j = 0; j < 8; j++) b[j] = Bs[kk][tx * 8 + j];
#pragma unroll
            for (int i = 0; i < 8; i++)
#pragma unroll
                for (int j = 0; j < 8; j++) acc[i][j] += a[i] * b[j];
        }
        __syncthreads();
    }

#pragma unroll
    for (int i = 0; i < 8; i++) {
        int r = row0 + ty * 8 + i;
        int b_ = r >> 11, n = r & (SEQ - 1);
#pragma unroll
        for (int j = 0; j < 8; j++) {
            int c = col0 + tx * 8 + j;
            float val = acc[i][j] + bias[c];
            int s = c >> 10;           // 0=Q 1=K 2=V
            int rr = c & (DIM - 1);
            int h = rr >> 6, d = rr & (HD - 1);
            float* dst = (s == 0) ? g_Q : (s == 1) ? g_K : g_V;
            dst[(((size_t)(b_ * HEADS + h) * SEQ) + n) * HD + d] = val;
        }
    }
}

// ---------------------------------------------------------------------------
// Flash-style attention, register-heavy version.
// Block: 64 queries of one (b,h); 256 threads; 4 threads per query row.
// t4 = tid&3: owns interleaved keys {t4+4j} and interleaved dim chunks
// {t4*4+16m .. +3} so every shared access is a conflict-free LDS.128/broadcast.
// Q row (64 floats) lives in registers. exp computed once per (q,k).
// ---------------------------------------------------------------------------
#define KT 32
#define KSTRIDE 68   // 64 + 4: float4-aligned, rows shift banks by 4

__global__ __launch_bounds__(256) void attn_kernel()
{
    __shared__ float Ks[KT][KSTRIDE];
    __shared__ float Vs[KT][KSTRIDE];
    __shared__ float Ss[64][36];
    __shared__ float Ms[64][4];
    __shared__ float Ls[64][4];

    const int tid = threadIdx.x;
    const int bh = blockIdx.y;
    const int q0 = blockIdx.x * 64;
    const int q  = tid >> 2;
    const int t4 = tid & 3;

    // Q row in registers, pre-scaled by 1/sqrt(hd)=0.125
    float4 qr[16];
    {
        const float4* Qg = (const float4*)(g_Q + ((size_t)bh * SEQ + q0 + q) * HD);
#pragma unroll
        for (int x = 0; x < 16; x++) {
            float4 v = Qg[x];
            v.x *= 0.125f; v.y *= 0.125f; v.z *= 0.125f; v.w *= 0.125f;
            qr[x] = v;
        }
    }

    float m_i = -1e30f, l_i = 0.f;
    float out[16];
#pragma unroll
    for (int d = 0; d < 16; d++) out[d] = 0.f;

    for (int kt = 0; kt < SEQ; kt += KT) {
        __syncthreads();   // protect Ks/Vs/Ss from previous iteration readers
        {
            const float4* Kg = (const float4*)(g_K + ((size_t)bh * SEQ + kt) * HD);
            const float4* Vg = (const float4*)(g_V + ((size_t)bh * SEQ + kt) * HD);
#pragma unroll
            for (int i = 0; i < 2; i++) {
                int idx = tid * 2 + i;          // 0..511
                int r = idx >> 4, c4 = (idx & 15);
                *(float4*)&Ks[r][c4 * 4] = Kg[r * 16 + c4];
                *(float4*)&Vs[r][c4 * 4] = Vg[r * 16 + c4];
            }
        }
        __syncthreads();

        // Phase 1: scores for this thread's 8 interleaved keys
        float s[8];
#pragma unroll
        for (int j = 0; j < 8; j++) {
            int k = t4 + 4 * j;
            const float4* Kr = (const float4*)&Ks[k][0];
            float acc = 0.f;
#pragma unroll
            for (int x = 0; x < 16; x++) {
                float4 kv = Kr[x];
                acc += qr[x].x * kv.x + qr[x].y * kv.y
                     + qr[x].z * kv.z + qr[x].w * kv.w;
            }
            s[j] = acc;
        }

        // Phase 2: online softmax (exp once per pair)
        float mloc = s[0];
#pragma unroll
        for (int j = 1; j < 8; j++) mloc = fmaxf(mloc, s[j]);
        Ms[q][t4] = mloc;
        __syncthreads();
        float mt = fmaxf(fmaxf(Ms[q][0], Ms[q][1]), fmaxf(Ms[q][2], Ms[q][3]));
        mt = fmaxf(mt, m_i);
        float corr = __expf(m_i - mt);
        m_i = mt;

        float lpart = 0.f;
#pragma unroll
        for (int j = 0; j < 8; j++) {
            float p = __expf(s[j] - mt);
            Ss[q][t4 + 4 * j] = p;
            lpart += p;
        }
        Ls[q][t4] = lpart;
        __syncthreads();
        l_i = l_i * corr + (Ls[q][0] + Ls[q][1]) + (Ls[q][2] + Ls[q][3]);

#pragma unroll
        for (int d = 0; d < 16; d++) out[d] *= corr;

        // Phase 3: out += P @ V over this tile (LDS.128 V, broadcast P)
#pragma unroll
        for (int k = 0; k < KT; k++) {
            float p = Ss[q][k];
            const float4* Vr = (const float4*)&Vs[k][0];
#pragma unroll
            for (int m = 0; m < 4; m++) {
                float4 v = Vr[t4 + 4 * m];
                out[m * 4 + 0] += p * v.x;
                out[m * 4 + 1] += p * v.y;
                out[m * 4 + 2] += p * v.z;
                out[m * 4 + 3] += p * v.w;
            }
        }
    }

    // Epilogue: normalize and write to [B,N,D] scratch
    const int b_ = bh >> 4, h = bh & 15;
    const float inv = 1.f / l_i;
    float* og = g_attn + ((size_t)(b_ * SEQ + q0 + q)) * DIM + h * HD;
#pragma unroll
    for (int m = 0; m < 4; m++) {
        float4 v;
        v.x = out[m * 4 + 0] * inv;
        v.y = out[m * 4 + 1] * inv;
        v.z = out[m * 4 + 2] * inv;
        v.w = out[m * 4 + 3] * inv;
        *(float4*)&og[t4 * 4 + 16 * m] = v;
    }
}

// ---------------------------------------------------------------------------
// GEMM 2: out = attn @ w_out + b_out
// ---------------------------------------------------------------------------
__global__ __launch_bounds__(256) void gemm_out(const float* __restrict__ W,
                                                const float* __restrict__ bias,
                                                float* __restrict__ out)
{
    const int K = DIM, Nc = DIM;
    const float* A = g_attn;
    __shared__ float As[16][128];
    __shared__ float Bs[16][128];

    const int tid = threadIdx.x;
    const int ty = tid >> 4, tx = tid & 15;
    const int row0 = blockIdx.y * 128, col0 = blockIdx.x * 128;

    float acc[8][8];
#pragma unroll
    for (int i = 0; i < 8; i++)
#pragma unroll
        for (int j = 0; j < 8; j++) acc[i][j] = 0.f;

    for (int k0 = 0; k0 < K; k0 += 16) {
#pragma unroll
        for (int i = 0; i < 2; i++) {
            int f = tid * 2 + i;
            int ar = f >> 2, ac = (f & 3) * 4;
            float4 v = *(const float4*)&A[(size_t)(row0 + ar) * K + k0 + ac];
            As[ac + 0][ar] = v.x; As[ac + 1][ar] = v.y;
            As[ac + 2][ar] = v.z; As[ac + 3][ar] = v.w;
        }
#pragma unroll
        for (int i = 0; i < 2; i++) {
            int f = tid * 2 + i;
            int br = f >> 5, bc = (f & 31) * 4;
            *(float4*)&Bs[br][bc] =
                *(const float4*)&W[(size_t)(k0 + br) * Nc + col0 + bc];
        }
        __syncthreads();

#pragma unroll
        for (int kk = 0; kk < 16; kk++) {
            float a[8], b[8];
#pragma unroll
            for (int i = 0; i < 8; i++) a[i] = As[kk][ty * 8 + i];
#pragma unroll
            for (int j = 0; j < 8; j++) b[j] = Bs[kk][tx * 8 + j];
#pragma unroll
            for (int i = 0; i < 8; i++)
#pragma unroll
                for (int j = 0; j < 8; j++) acc[i][j] += a[i] * b[j];
        }
        __syncthreads();
    }

#pragma unroll
    for (int i = 0; i < 8; i++) {
        int r = row0 + ty * 8 + i;
#pragma unroll
        for (int j = 0; j < 8; j += 4) {
            int c = col0 + tx * 8 + j;
            float4 v;
            v.x = acc[i][j + 0] + bias[c + 0];
            v.y = acc[i][j + 1] + bias[c + 1];
            v.z = acc[i][j + 2] + bias[c + 2];
            v.w = acc[i][j + 3] + bias[c + 3];
            *(float4*)&out[(size_t)r * Nc + c] = v;
        }
    }
}

extern "C" void kernel_launch(void* const* d_in, const int* in_sizes, int n_in,
                              void* d_out, int out_size)
{
    (void)in_sizes; (void)n_in; (void)out_size;
    const float* x     = (const float*)d_in[0];
    const float* w_qkv = (const float*)d_in[1];
    const float* b_qkv = (const float*)d_in[2];
    const float* w_out = (const float*)d_in[3];
    const float* b_out = (const float*)d_in[4];
    float* out = (float*)d_out;

    gemm_qkv<<<dim3(QKV_N / 128, MROWS / 128), 256>>>(x, w_qkv, b_qkv);
    attn_kernel<<<dim3(SEQ / 64, BATCH * HEADS), 256>>>();
    gemm_out<<<dim3(DIM / 128, MROWS / 128), 256>>>(w_out, b_out, out);
}

// round 4
// speedup vs baseline: 1.2547x; 1.0043x over previous
#include <cuda_runtime.h>

#define BATCH 2
#define HEADS 16
#define SEQ   2048
#define DIM   1024
#define HD    64
#define QKV_N (3*DIM)
#define MROWS (BATCH*SEQ)   // 4096

// Scratch (no allocations allowed)
__device__ float g_Q[BATCH*HEADS*SEQ*HD];
__device__ float g_K[BATCH*HEADS*SEQ*HD];
__device__ float g_V[BATCH*HEADS*SEQ*HD];
__device__ float g_attn[BATCH*SEQ*DIM];

// ---------------------------------------------------------------------------
// GEMM 1: qkv = x @ w_qkv + b_qkv, scattered to [B,H,N,hd] Q/K/V tensors.
// Double-buffered smem, register-staged prefetch, 1 sync per k-tile.
// ---------------------------------------------------------------------------
__global__ __launch_bounds__(256) void gemm_qkv(const float* __restrict__ A,
                                                const float* __restrict__ W,
                                                const float* __restrict__ bias)
{
    const int K = DIM, Nc = QKV_N;
    __shared__ float As[2][16][128];
    __shared__ float Bs[2][16][128];

    const int tid = threadIdx.x;
    const int ty = tid >> 4, tx = tid & 15;
    const int row0 = blockIdx.y * 128, col0 = blockIdx.x * 128;

    const int ar = (tid * 2) >> 2,  ac = ((tid * 2) & 3) * 4;       // A tile coords (i=0)
    const int ar1 = (tid * 2 + 1) >> 2, ac1 = ((tid * 2 + 1) & 3) * 4;
    const int br = (tid * 2) >> 5,  bc = ((tid * 2) & 31) * 4;
    const int br1 = (tid * 2 + 1) >> 5, bc1 = ((tid * 2 + 1) & 31) * 4;

    float acc[8][8];
#pragma unroll
    for (int i = 0; i < 8; i++)
#pragma unroll
        for (int j = 0; j < 8; j++) acc[i][j] = 0.f;

    // Prologue: fetch k-tile 0 into registers
    float4 aReg0 = *(const float4*)&A[(size_t)(row0 + ar)  * K + ac];
    float4 aReg1 = *(const float4*)&A[(size_t)(row0 + ar1) * K + ac1];
    float4 bReg0 = *(const float4*)&W[(size_t)br  * Nc + col0 + bc];
    float4 bReg1 = *(const float4*)&W[(size_t)br1 * Nc + col0 + bc1];

    int p = 0;
    for (int k0 = 0; k0 < K; k0 += 16) {
        // Stage registers -> smem buffer p
        As[p][ac  + 0][ar ] = aReg0.x; As[p][ac  + 1][ar ] = aReg0.y;
        As[p][ac  + 2][ar ] = aReg0.z; As[p][ac  + 3][ar ] = aReg0.w;
        As[p][ac1 + 0][ar1] = aReg1.x; As[p][ac1 + 1][ar1] = aReg1.y;
        As[p][ac1 + 2][ar1] = aReg1.z; As[p][ac1 + 3][ar1] = aReg1.w;
        *(float4*)&Bs[p][br ][bc ] = bReg0;
        *(float4*)&Bs[p][br1][bc1] = bReg1;

        // Prefetch next k-tile
        if (k0 + 16 < K) {
            aReg0 = *(const float4*)&A[(size_t)(row0 + ar)  * K + (k0 + 16) + ac];
            aReg1 = *(const float4*)&A[(size_t)(row0 + ar1) * K + (k0 + 16) + ac1];
            bReg0 = *(const float4*)&W[(size_t)(k0 + 16 + br)  * Nc + col0 + bc];
            bReg1 = *(const float4*)&W[(size_t)(k0 + 16 + br1) * Nc + col0 + bc1];
        }
        __syncthreads();

#pragma unroll
        for (int kk = 0; kk < 16; kk++) {
            float a[8], b[8];
#pragma unroll
            for (int i = 0; i < 8; i++) a[i] = As[p][kk][ty * 8 + i];
#pragma unroll
            for (int j = 0; j < 8; j++) b[j] = Bs[p][kk][tx * 8 + j];
#pragma unroll
            for (int i = 0; i < 8; i++)
#pragma unroll
                for (int j = 0; j < 8; j++) acc[i][j] += a[i] * b[j];
        }
        p ^= 1;
    }

#pragma unroll
    for (int i = 0; i < 8; i++) {
        int r = row0 + ty * 8 + i;
        int b_ = r >> 11, n = r & (SEQ - 1);
#pragma unroll
        for (int j = 0; j < 8; j++) {
            int c = col0 + tx * 8 + j;
            float val = acc[i][j] + bias[c];
            int s = c >> 10;           // 0=Q 1=K 2=V
            int rr = c & (DIM - 1);
            int h = rr >> 6, d = rr & (HD - 1);
            float* dst = (s == 0) ? g_Q : (s == 1) ? g_K : g_V;
            dst[(((size_t)(b_ * HEADS + h) * SEQ) + n) * HD + d] = val;
        }
    }
}

// ---------------------------------------------------------------------------
// Flash-style attention. 64 queries/block, 256 threads, 4 threads/row.
// Q in registers; double-buffered K/V smem (1 block sync per tile);
// softmax reductions via shfl within the 4-lane row group; Ss hand-off
// via __syncwarp. 4 independent FMA chains per dot.
// ---------------------------------------------------------------------------
#define KT 32
#define KSTRIDE 68   // 64 + 4: float4-aligned, rows shift banks by 4

__global__ __launch_bounds__(256) void attn_kernel()
{
    __shared__ float Ks[2][KT][KSTRIDE];
    __shared__ float Vs[2][KT][KSTRIDE];
    __shared__ float Ss[64][36];

    const int tid = threadIdx.x;
    const int bh = blockIdx.y;
    const int q0 = blockIdx.x * 64;
    const int q  = tid >> 2;
    const int t4 = tid & 3;

    // Q row in registers, pre-scaled by 1/sqrt(hd)=0.125
    float4 qr[16];
    {
        const float4* Qg = (const float4*)(g_Q + ((size_t)bh * SEQ + q0 + q) * HD);
#pragma unroll
        for (int x = 0; x < 16; x++) {
            float4 v = Qg[x];
            v.x *= 0.125f; v.y *= 0.125f; v.z *= 0.125f; v.w *= 0.125f;
            qr[x] = v;
        }
    }

    float m_i = -1e30f, l_i = 0.f;
    float out[16];
#pragma unroll
    for (int d = 0; d < 16; d++) out[d] = 0.f;

    // Per-thread staging coords: 2 float4 each of K and V per tile
    const int idx0 = tid * 2, idx1 = tid * 2 + 1;
    const int r0 = idx0 >> 4, c0 = idx0 & 15;
    const int r1 = idx1 >> 4, c1 = idx1 & 15;
    const float* Kbase = g_K + (size_t)bh * SEQ * HD;
    const float* Vbase = g_V + (size_t)bh * SEQ * HD;

    // Prologue: fetch tile 0
    float4 kreg0 = ((const float4*)(Kbase))[r0 * 16 + c0];
    float4 kreg1 = ((const float4*)(Kbase))[r1 * 16 + c1];
    float4 vreg0 = ((const float4*)(Vbase))[r0 * 16 + c0];
    float4 vreg1 = ((const float4*)(Vbase))[r1 * 16 + c1];

    int p = 0;
    for (int kt = 0; kt < SEQ; kt += KT) {
        // Stage current tile into buffer p
        *(float4*)&Ks[p][r0][c0 * 4] = kreg0;
        *(float4*)&Ks[p][r1][c1 * 4] = kreg1;
        *(float4*)&Vs[p][r0][c0 * 4] = vreg0;
        *(float4*)&Vs[p][r1][c1 * 4] = vreg1;

        // Prefetch next tile
        if (kt + KT < SEQ) {
            const float4* Kg = (const float4*)(Kbase + (size_t)(kt + KT) * HD);
            const float4* Vg = (const float4*)(Vbase + (size_t)(kt + KT) * HD);
            kreg0 = Kg[r0 * 16 + c0];
            kreg1 = Kg[r1 * 16 + c1];
            vreg0 = Vg[r0 * 16 + c0];
            vreg1 = Vg[r1 * 16 + c1];
        }
        __syncthreads();

        // Phase 1: scores for 8 interleaved keys, 4 chains per dot
        float s[8];
#pragma unroll
        for (int j = 0; j < 8; j++) {
            int k = t4 + 4 * j;
            const float4* Kr = (const float4*)&Ks[p][k][0];
            float ax = 0.f, ay = 0.f, az = 0.f, aw = 0.f;
#pragma unroll
            for (int x = 0; x < 16; x++) {
                float4 kv = Kr[x];
                ax += qr[x].x * kv.x; ay += qr[x].y * kv.y;
                az += qr[x].z * kv.z; aw += qr[x].w * kv.w;
            }
            s[j] = (ax + ay) + (az + aw);
        }

        // Phase 2: online softmax, reductions via shfl over the 4-lane group
        float mloc = s[0];
#pragma unroll
        for (int j = 1; j < 8; j++) mloc = fmaxf(mloc, s[j]);
        mloc = fmaxf(mloc, __shfl_xor_sync(0xFFFFFFFFu, mloc, 1));
        mloc = fmaxf(mloc, __shfl_xor_sync(0xFFFFFFFFu, mloc, 2));
        float mt = fmaxf(mloc, m_i);
        float corr = __expf(m_i - mt);
        m_i = mt;

        float lpart = 0.f;
#pragma unroll
        for (int j = 0; j < 8; j++) {
            float pe = __expf(s[j] - mt);
            Ss[q][t4 + 4 * j] = pe;
            lpart += pe;
        }
        lpart += __shfl_xor_sync(0xFFFFFFFFu, lpart, 1);
        lpart += __shfl_xor_sync(0xFFFFFFFFu, lpart, 2);
        l_i = l_i * corr + lpart;

#pragma unroll
        for (int d = 0; d < 16; d++) out[d] *= corr;

        __syncwarp();   // Ss writers/readers are within one warp

        // Phase 3: out += P @ V (LDS.128 V, broadcast P)
#pragma unroll
        for (int k = 0; k < KT; k++) {
            float pe = Ss[q][k];
            const float4* Vr = (const float4*)&Vs[p][k][0];
#pragma unroll
            for (int m = 0; m < 4; m++) {
                float4 v = Vr[t4 + 4 * m];
                out[m * 4 + 0] += pe * v.x;
                out[m * 4 + 1] += pe * v.y;
                out[m * 4 + 2] += pe * v.z;
                out[m * 4 + 3] += pe * v.w;
            }
        }
        __syncwarp();   // protect Ss from next iteration's writes
        p ^= 1;
    }

    // Epilogue: normalize and write to [B,N,D] scratch
    const int b_ = bh >> 4, h = bh & 15;
    const float inv = 1.f / l_i;
    float* og = g_attn + ((size_t)(b_ * SEQ + q0 + q)) * DIM + h * HD;
#pragma unroll
    for (int m = 0; m < 4; m++) {
        float4 v;
        v.x = out[m * 4 + 0] * inv;
        v.y = out[m * 4 + 1] * inv;
        v.z = out[m * 4 + 2] * inv;
        v.w = out[m * 4 + 3] * inv;
        *(float4*)&og[t4 * 4 + 16 * m] = v;
    }
}

// ---------------------------------------------------------------------------
// GEMM 2: out = attn @ w_out + b_out (same pipelined structure)
// ---------------------------------------------------------------------------
__global__ __launch_bounds__(256) void gemm_out(const float* __restrict__ W,
                                                const float* __restrict__ bias,
                                                float* __restrict__ out)
{
    const int K = DIM, Nc = DIM;
    const float* A = g_attn;
    __shared__ float As[2][16][128];
    __shared__ float Bs[2][16][128];

    const int tid = threadIdx.x;
    const int ty = tid >> 4, tx = tid & 15;
    const int row0 = blockIdx.y * 128, col0 = blockIdx.x * 128;

    const int ar = (tid * 2) >> 2,  ac = ((tid * 2) & 3) * 4;
    const int ar1 = (tid * 2 + 1) >> 2, ac1 = ((tid * 2 + 1) & 3) * 4;
    const int br = (tid * 2) >> 5,  bc = ((tid * 2) & 31) * 4;
    const int br1 = (tid * 2 + 1) >> 5, bc1 = ((tid * 2 + 1) & 31) * 4;

    float acc[8][8];
#pragma unroll
    for (int i = 0; i < 8; i++)
#pragma unroll
        for (int j = 0; j < 8; j++) acc[i][j] = 0.f;

    float4 aReg0 = *(const float4*)&A[(size_t)(row0 + ar)  * K + ac];
    float4 aReg1 = *(const float4*)&A[(size_t)(row0 + ar1) * K + ac1];
    float4 bReg0 = *(const float4*)&W[(size_t)br  * Nc + col0 + bc];
    float4 bReg1 = *(const float4*)&W[(size_t)br1 * Nc + col0 + bc1];

    int p = 0;
    for (int k0 = 0; k0 < K; k0 += 16) {
        As[p][ac  + 0][ar ] = aReg0.x; As[p][ac  + 1][ar ] = aReg0.y;
        As[p][ac  + 2][ar ] = aReg0.z; As[p][ac  + 3][ar ] = aReg0.w;
        As[p][ac1 + 0][ar1] = aReg1.x; As[p][ac1 + 1][ar1] = aReg1.y;
        As[p][ac1 + 2][ar1] = aReg1.z; As[p][ac1 + 3][ar1] = aReg1.w;
        *(float4*)&Bs[p][br ][bc ] = bReg0;
        *(float4*)&Bs[p][br1][bc1] = bReg1;

        if (k0 + 16 < K) {
            aReg0 = *(const float4*)&A[(size_t)(row0 + ar)  * K + (k0 + 16) + ac];
            aReg1 = *(const float4*)&A[(size_t)(row0 + ar1) * K + (k0 + 16) + ac1];
            bReg0 = *(const float4*)&W[(size_t)(k0 + 16 + br)  * Nc + col0 + bc];
            bReg1 = *(const float4*)&W[(size_t)(k0 + 16 + br1) * Nc + col0 + bc1];
        }
        __syncthreads();

#pragma unroll
        for (int kk = 0; kk < 16; kk++) {
            float a[8], b[8];
#pragma unroll
            for (int i = 0; i < 8; i++) a[i] = As[p][kk][ty * 8 + i];
#pragma unroll
            for (int j = 0; j < 8; j++) b[j] = Bs[p][kk][tx * 8 + j];
#pragma unroll
            for (int i = 0; i < 8; i++)
#pragma unroll
                for (int j = 0; j < 8; j++) acc[i][j] += a[i] * b[j];
        }
        p ^= 1;
    }

#pragma unroll
    for (int i = 0; i < 8; i++) {
        int r = row0 + ty * 8 + i;
#pragma unroll
        for (int j = 0; j < 8; j += 4) {
            int c = col0 + tx * 8 + j;
            float4 v;
            v.x = acc[i][j + 0] + bias[c + 0];
            v.y = acc[i][j + 1] + bias[c + 1];
            v.z = acc[i][j + 2] + bias[c + 2];
            v.w = acc[i][j + 3] + bias[c + 3];
            *(float4*)&out[(size_t)r * Nc + c] = v;
        }
    }
}

extern "C" void kernel_launch(void* const* d_in, const int* in_sizes, int n_in,
                              void* d_out, int out_size)
{
    (void)in_sizes; (void)n_in; (void)out_size;
    const float* x     = (const float*)d_in[0];
    const float* w_qkv = (const float*)d_in[1];
    const float* b_qkv = (const float*)d_in[2];
    const float* w_out = (const float*)d_in[3];
    const float* b_out = (const float*)d_in[4];
    float* out = (float*)d_out;

    gemm_qkv<<<dim3(QKV_N / 128, MROWS / 128), 256>>>(x, w_qkv, b_qkv);
    attn_kernel<<<dim3(SEQ / 64, BATCH * HEADS), 256>>>();
    gemm_out<<<dim3(DIM / 128, MROWS / 128), 256>>>(w_out, b_out, out);
}

// round 5
// speedup vs baseline: 3.0024x; 2.3929x over previous
#include <cuda_runtime.h>
#include <cuda_bf16.h>

#define BATCH 2
#define HEADS 16
#define SEQ   2048
#define DIM   1024
#define HD    64
#define QKV_N (3*DIM)
#define MROWS (BATCH*SEQ)   // 4096
#define BH    (BATCH*HEADS) // 32

// fp32 scratch
__device__ float g_Q[BATCH*HEADS*SEQ*HD];
__device__ float g_K[BATCH*HEADS*SEQ*HD];
__device__ float g_V[BATCH*HEADS*SEQ*HD];
__device__ float g_attn[BATCH*SEQ*DIM];
// bf16 hi/lo split scratch
__device__ __nv_bfloat16 g_Qh[BATCH*HEADS*SEQ*HD];
__device__ __nv_bfloat16 g_Ql[BATCH*HEADS*SEQ*HD];
__device__ __nv_bfloat16 g_Kh[BATCH*HEADS*SEQ*HD];
__device__ __nv_bfloat16 g_Kl[BATCH*HEADS*SEQ*HD];
__device__ __nv_bfloat16 g_Vth[BATCH*HEADS*HD*SEQ];  // transposed [bh][hd][seq]
__device__ __nv_bfloat16 g_Vtl[BATCH*HEADS*HD*SEQ];

// ---------------------------------------------------------------------------
// GEMM 1 (R3 version): qkv = x @ w_qkv + b_qkv -> fp32 Q/K/V [bh][n][hd]
// ---------------------------------------------------------------------------
__global__ __launch_bounds__(256) void gemm_qkv(const float* __restrict__ A,
                                                const float* __restrict__ W,
                                                const float* __restrict__ bias)
{
    const int K = DIM, Nc = QKV_N;
    __shared__ float As[16][128];
    __shared__ float Bs[16][128];

    const int tid = threadIdx.x;
    const int ty = tid >> 4, tx = tid & 15;
    const int row0 = blockIdx.y * 128, col0 = blockIdx.x * 128;

    float acc[8][8];
#pragma unroll
    for (int i = 0; i < 8; i++)
#pragma unroll
        for (int j = 0; j < 8; j++) acc[i][j] = 0.f;

    for (int k0 = 0; k0 < K; k0 += 16) {
#pragma unroll
        for (int i = 0; i < 2; i++) {
            int f = tid * 2 + i;
            int ar = f >> 2, ac = (f & 3) * 4;
            float4 v = *(const float4*)&A[(size_t)(row0 + ar) * K + k0 + ac];
            As[ac + 0][ar] = v.x; As[ac + 1][ar] = v.y;
            As[ac + 2][ar] = v.z; As[ac + 3][ar] = v.w;
        }
#pragma unroll
        for (int i = 0; i < 2; i++) {
            int f = tid * 2 + i;
            int br = f >> 5, bc = (f & 31) * 4;
            *(float4*)&Bs[br][bc] =
                *(const float4*)&W[(size_t)(k0 + br) * Nc + col0 + bc];
        }
        __syncthreads();

#pragma unroll
        for (int kk = 0; kk < 16; kk++) {
            float a[8], b[8];
#pragma unroll
            for (int i = 0; i < 8; i++) a[i] = As[kk][ty * 8 + i];
#pragma unroll
            for (int j = 0; j < 8; j++) b[j] = Bs[kk][tx * 8 + j];
#pragma unroll
            for (int i = 0; i < 8; i++)
#pragma unroll
                for (int j = 0; j < 8; j++) acc[i][j] += a[i] * b[j];
        }
        __syncthreads();
    }

#pragma unroll
    for (int i = 0; i < 8; i++) {
        int r = row0 + ty * 8 + i;
        int b_ = r >> 11, n = r & (SEQ - 1);
#pragma unroll
        for (int j = 0; j < 8; j++) {
            int c = col0 + tx * 8 + j;
            float val = acc[i][j] + bias[c];
            int s = c >> 10;
            int rr = c & (DIM - 1);
            int h = rr >> 6, d = rr & (HD - 1);
            float* dst = (s == 0) ? g_Q : (s == 1) ? g_K : g_V;
            dst[(((size_t)(b_ * HEADS + h) * SEQ) + n) * HD + d] = val;
        }
    }
}

// ---------------------------------------------------------------------------
// Convert: fp32 Q/K/V -> bf16 hi/lo; Q pre-scaled by 0.125; V transposed.
// Block handles one (bh, 64-row seq tile).
// ---------------------------------------------------------------------------
__global__ __launch_bounds__(256) void convert_split()
{
    __shared__ float vt[64][65];
    const int bh = blockIdx.y;
    const int s0 = blockIdx.x * 64;
    const int tid = threadIdx.x;
    const size_t base = ((size_t)bh * SEQ + s0) * HD;

    for (int i = tid; i < 64 * HD; i += 256) {
        int s = i >> 6, d = i & 63;
        size_t idx = base + i;
        float q = g_Q[idx] * 0.125f;
        __nv_bfloat16 qh = __float2bfloat16(q);
        g_Qh[idx] = qh;
        g_Ql[idx] = __float2bfloat16(q - __bfloat162float(qh));
        float k = g_K[idx];
        __nv_bfloat16 kh = __float2bfloat16(k);
        g_Kh[idx] = kh;
        g_Kl[idx] = __float2bfloat16(k - __bfloat162float(kh));
        vt[s][d] = g_V[idx];
    }
    __syncthreads();
    for (int i = tid; i < 64 * HD; i += 256) {
        int d = i >> 6, s = i & 63;
        float v = vt[s][d];
        __nv_bfloat16 vh = __float2bfloat16(v);
        size_t o = ((size_t)bh * HD + d) * SEQ + s0 + s;
        g_Vth[o] = vh;
        g_Vtl[o] = __float2bfloat16(v - __bfloat162float(vh));
    }
}

// ---------------------------------------------------------------------------
// mma.sync helpers
// ---------------------------------------------------------------------------
__device__ __forceinline__ void mma16816(float* c,
    unsigned a0, unsigned a1, unsigned a2, unsigned a3,
    unsigned b0, unsigned b1)
{
    asm volatile(
        "mma.sync.aligned.m16n8k16.row.col.f32.bf16.bf16.f32 "
        "{%0,%1,%2,%3}, {%4,%5,%6,%7}, {%8,%9}, {%0,%1,%2,%3};"
        : "+f"(c[0]), "+f"(c[1]), "+f"(c[2]), "+f"(c[3])
        : "r"(a0), "r"(a1), "r"(a2), "r"(a3), "r"(b0), "r"(b1));
}

// pack two floats into bf16x2 hi/lo-split pairs
__device__ __forceinline__ void bsplit2(float x, float y,
                                        unsigned& hi, unsigned& lo)
{
    __nv_bfloat162 h2, l2;
    h2.x = __float2bfloat16(x);
    h2.y = __float2bfloat16(y);
    l2.x = __float2bfloat16(x - __bfloat162float(h2.x));
    l2.y = __float2bfloat16(y - __bfloat162float(h2.y));
    hi = *reinterpret_cast<unsigned*>(&h2);
    lo = *reinterpret_cast<unsigned*>(&l2);
}

// ---------------------------------------------------------------------------
// Tensor-core flash attention. 128 threads = 4 warps; warp w owns queries
// [q0 + 16w, q0 + 16w + 16). Key tiles of 32. 3-term bf16 split MMA for
// both QK^T and PV. Register softmax (FA2).
//   KSP = 72 (K tile row pad), VSP = 40 (Vt row pad): fragment-load banks
//   (2tig + row*pad/2 words) are all-distinct across the warp.
// ---------------------------------------------------------------------------
#define KSP 72
#define VSP 40

__global__ __launch_bounds__(128) void attn_mma()
{
    __shared__ __nv_bfloat16 Ksh[32][KSP];
    __shared__ __nv_bfloat16 Ksl[32][KSP];
    __shared__ __nv_bfloat16 Vsh[HD][VSP];
    __shared__ __nv_bfloat16 Vsl[HD][VSP];

    const int tid  = threadIdx.x;
    const int warp = tid >> 5;
    const int lane = tid & 31;
    const int g    = lane >> 2;   // group (row) id 0..7
    const int tig  = lane & 3;    // thread in group

    const int bh = blockIdx.y;
    const int q0 = blockIdx.x * 64;
    const int qbase = q0 + warp * 16;

    // --- Q fragments (hi/lo), loaded once from gmem ---
    unsigned aqh[4][4], aql[4][4];
    {
        const __nv_bfloat16* Qh = g_Qh + ((size_t)bh * SEQ + qbase) * HD;
        const __nv_bfloat16* Ql = g_Ql + ((size_t)bh * SEQ + qbase) * HD;
#pragma unroll
        for (int kc = 0; kc < 4; kc++) {
            int d0 = 16 * kc + 2 * tig;
            aqh[kc][0] = *(const unsigned*)&Qh[(size_t)g * HD + d0];
            aqh[kc][1] = *(const unsigned*)&Qh[(size_t)(g + 8) * HD + d0];
            aqh[kc][2] = *(const unsigned*)&Qh[(size_t)g * HD + d0 + 8];
            aqh[kc][3] = *(const unsigned*)&Qh[(size_t)(g + 8) * HD + d0 + 8];
            aql[kc][0] = *(const unsigned*)&Ql[(size_t)g * HD + d0];
            aql[kc][1] = *(const unsigned*)&Ql[(size_t)(g + 8) * HD + d0];
            aql[kc][2] = *(const unsigned*)&Ql[(size_t)g * HD + d0 + 8];
            aql[kc][3] = *(const unsigned*)&Ql[(size_t)(g + 8) * HD + d0 + 8];
        }
    }

    float oacc[8][4];
#pragma unroll
    for (int dt = 0; dt < 8; dt++)
#pragma unroll
        for (int e = 0; e < 4; e++) oacc[dt][e] = 0.f;
    float m0 = -1e30f, m1 = -1e30f, l0 = 0.f, l1 = 0.f;

    const __nv_bfloat16* Khg = g_Kh + (size_t)bh * SEQ * HD;
    const __nv_bfloat16* Klg = g_Kl + (size_t)bh * SEQ * HD;
    const __nv_bfloat16* Vthg = g_Vth + (size_t)bh * HD * SEQ;
    const __nv_bfloat16* Vtlg = g_Vtl + (size_t)bh * HD * SEQ;

    for (int kt = 0; kt < SEQ; kt += 32) {
        __syncthreads();
        // Stage K tile (32x64) and Vt tile (64x32), hi+lo
#pragma unroll
        for (int c = 0; c < 2; c++) {
            int i = tid + c * 128;
            int r = i >> 3, seg = i & 7;               // K: 32 rows x 8 segs
            const size_t ko = (size_t)(kt + r) * HD + seg * 8;
            *(float4*)&Ksh[r][seg * 8] = *(const float4*)&Khg[ko];
            *(float4*)&Ksl[r][seg * 8] = *(const float4*)&Klg[ko];
            int rv = i >> 2, sv = i & 3;               // Vt: 64 rows x 4 segs
            const size_t vo = (size_t)rv * SEQ + kt + sv * 8;
            *(float4*)&Vsh[rv][sv * 8] = *(const float4*)&Vthg[vo];
            *(float4*)&Vsl[rv][sv * 8] = *(const float4*)&Vtlg[vo];
        }
        __syncthreads();

        // --- scores: S[16 q][32 keys] in 4 n8 tiles ---
        float sacc[4][4];
#pragma unroll
        for (int j = 0; j < 4; j++) {
#pragma unroll
            for (int e = 0; e < 4; e++) sacc[j][e] = 0.f;
            int key = 8 * j + g;
#pragma unroll
            for (int kc = 0; kc < 4; kc++) {
                int d0 = 16 * kc + 2 * tig;
                unsigned bh0 = *(const unsigned*)&Ksh[key][d0];
                unsigned bh1 = *(const unsigned*)&Ksh[key][d0 + 8];
                unsigned bl0 = *(const unsigned*)&Ksl[key][d0];
                unsigned bl1 = *(const unsigned*)&Ksl[key][d0 + 8];
                mma16816(sacc[j], aqh[kc][0], aqh[kc][1], aqh[kc][2], aqh[kc][3], bh0, bh1);
                mma16816(sacc[j], aqh[kc][0], aqh[kc][1], aqh[kc][2], aqh[kc][3], bl0, bl1);
                mma16816(sacc[j], aql[kc][0], aql[kc][1], aql[kc][2], aql[kc][3], bh0, bh1);
            }
        }

        // --- online softmax on fragments ---
        float r0 = -1e30f, r1 = -1e30f;
#pragma unroll
        for (int j = 0; j < 4; j++) {
            r0 = fmaxf(r0, fmaxf(sacc[j][0], sacc[j][1]));
            r1 = fmaxf(r1, fmaxf(sacc[j][2], sacc[j][3]));
        }
        r0 = fmaxf(r0, __shfl_xor_sync(0xFFFFFFFFu, r0, 1));
        r0 = fmaxf(r0, __shfl_xor_sync(0xFFFFFFFFu, r0, 2));
        r1 = fmaxf(r1, __shfl_xor_sync(0xFFFFFFFFu, r1, 1));
        r1 = fmaxf(r1, __shfl_xor_sync(0xFFFFFFFFu, r1, 2));
        float mn0 = fmaxf(m0, r0), mn1 = fmaxf(m1, r1);
        float corr0 = __expf(m0 - mn0), corr1 = __expf(m1 - mn1);
        m0 = mn0; m1 = mn1;

        float ls0 = 0.f, ls1 = 0.f;
#pragma unroll
        for (int j = 0; j < 4; j++) {
            sacc[j][0] = __expf(sacc[j][0] - mn0);
            sacc[j][1] = __expf(sacc[j][1] - mn0);
            sacc[j][2] = __expf(sacc[j][2] - mn1);
            sacc[j][3] = __expf(sacc[j][3] - mn1);
            ls0 += sacc[j][0] + sacc[j][1];
            ls1 += sacc[j][2] + sacc[j][3];
        }
        ls0 += __shfl_xor_sync(0xFFFFFFFFu, ls0, 1);
        ls0 += __shfl_xor_sync(0xFFFFFFFFu, ls0, 2);
        ls1 += __shfl_xor_sync(0xFFFFFFFFu, ls1, 1);
        ls1 += __shfl_xor_sync(0xFFFFFFFFu, ls1, 2);
        l0 = l0 * corr0 + ls0;
        l1 = l1 * corr1 + ls1;

#pragma unroll
        for (int dt = 0; dt < 8; dt++) {
            oacc[dt][0] *= corr0; oacc[dt][1] *= corr0;
            oacc[dt][2] *= corr1; oacc[dt][3] *= corr1;
        }

        // --- P fragments (C layout == A layout), bf16 hi/lo ---
        unsigned aph[2][4], apl[2][4];
#pragma unroll
        for (int kc2 = 0; kc2 < 2; kc2++) {
            int j0 = 2 * kc2, j1 = 2 * kc2 + 1;
            bsplit2(sacc[j0][0], sacc[j0][1], aph[kc2][0], apl[kc2][0]);
            bsplit2(sacc[j0][2], sacc[j0][3], aph[kc2][1], apl[kc2][1]);
            bsplit2(sacc[j1][0], sacc[j1][1], aph[kc2][2], apl[kc2][2]);
            bsplit2(sacc[j1][2], sacc[j1][3], aph[kc2][3], apl[kc2][3]);
        }

        // --- PV: out[16 q][64 dims] ---
#pragma unroll
        for (int dt = 0; dt < 8; dt++) {
            int drow = 8 * dt + g;
#pragma unroll
            for (int kc2 = 0; kc2 < 2; kc2++) {
                int k0c = 16 * kc2 + 2 * tig;
                unsigned bh0 = *(const unsigned*)&Vsh[drow][k0c];
                unsigned bh1 = *(const unsigned*)&Vsh[drow][k0c + 8];
                unsigned bl0 = *(const unsigned*)&Vsl[drow][k0c];
                unsigned bl1 = *(const unsigned*)&Vsl[drow][k0c + 8];
                mma16816(oacc[dt], aph[kc2][0], aph[kc2][1], aph[kc2][2], aph[kc2][3], bh0, bh1);
                mma16816(oacc[dt], aph[kc2][0], aph[kc2][1], aph[kc2][2], aph[kc2][3], bl0, bl1);
                mma16816(oacc[dt], apl[kc2][0], apl[kc2][1], apl[kc2][2], apl[kc2][3], bh0, bh1);
            }
        }
    }

    // --- epilogue: normalize, write to g_attn [B,N,D] ---
    const int b_ = bh >> 4, h = bh & 15;
    const float inv0 = 1.f / l0, inv1 = 1.f / l1;
    const int qg0 = qbase + g, qg1 = qbase + g + 8;
    float* o0 = g_attn + ((size_t)(b_ * SEQ + qg0)) * DIM + h * HD;
    float* o1 = g_attn + ((size_t)(b_ * SEQ + qg1)) * DIM + h * HD;
#pragma unroll
    for (int dt = 0; dt < 8; dt++) {
        int d = 8 * dt + 2 * tig;
        float2 v0 = make_float2(oacc[dt][0] * inv0, oacc[dt][1] * inv0);
        float2 v1 = make_float2(oacc[dt][2] * inv1, oacc[dt][3] * inv1);
        *(float2*)&o0[d] = v0;
        *(float2*)&o1[d] = v1;
    }
}

// ---------------------------------------------------------------------------
// GEMM 2 (R3 version): out = attn @ w_out + b_out
// ---------------------------------------------------------------------------
__global__ __launch_bounds__(256) void gemm_out(const float* __restrict__ W,
                                                const float* __restrict__ bias,
                                                float* __restrict__ out)
{
    const int K = DIM, Nc = DIM;
    const float* A = g_attn;
    __shared__ float As[16][128];
    __shared__ float Bs[16][128];

    const int tid = threadIdx.x;
    const int ty = tid >> 4, tx = tid & 15;
    const int row0 = blockIdx.y * 128, col0 = blockIdx.x * 128;

    float acc[8][8];
#pragma unroll
    for (int i = 0; i < 8; i++)
#pragma unroll
        for (int j = 0; j < 8; j++) acc[i][j] = 0.f;

    for (int k0 = 0; k0 < K; k0 += 16) {
#pragma unroll
        for (int i = 0; i < 2; i++) {
            int f = tid * 2 + i;
            int ar = f >> 2, ac = (f & 3) * 4;
            float4 v = *(const float4*)&A[(size_t)(row0 + ar) * K + k0 + ac];
            As[ac + 0][ar] = v.x; As[ac + 1][ar] = v.y;
            As[ac + 2][ar] = v.z; As[ac + 3][ar] = v.w;
        }
#pragma unroll
        for (int i = 0; i < 2; i++) {
            int f = tid * 2 + i;
            int br = f >> 5, bc = (f & 31) * 4;
            *(float4*)&Bs[br][bc] =
                *(const float4*)&W[(size_t)(k0 + br) * Nc + col0 + bc];
        }
        __syncthreads();

#pragma unroll
        for (int kk = 0; kk < 16; kk++) {
            float a[8], b[8];
#pragma unroll
            for (int i = 0; i < 8; i++) a[i] = As[kk][ty * 8 + i];
#pragma unroll
            for (int j = 0; j < 8; j++) b[j] = Bs[kk][tx * 8 + j];
#pragma unroll
            for (int i = 0; i < 8; i++)
#pragma unroll
                for (int j = 0; j < 8; j++) acc[i][j] += a[i] * b[j];
        }
        __syncthreads();
    }

#pragma unroll
    for (int i = 0; i < 8; i++) {
        int r = row0 + ty * 8 + i;
#pragma unroll
        for (int j = 0; j < 8; j += 4) {
            int c = col0 + tx * 8 + j;
            float4 v;
            v.x = acc[i][j + 0] + bias[c + 0];
            v.y = acc[i][j + 1] + bias[c + 1];
            v.z = acc[i][j + 2] + bias[c + 2];
            v.w = acc[i][j + 3] + bias[c + 3];
            *(float4*)&out[(size_t)r * Nc + c] = v;
        }
    }
}

extern "C" void kernel_launch(void* const* d_in, const int* in_sizes, int n_in,
                              void* d_out, int out_size)
{
    (void)in_sizes; (void)n_in; (void)out_size;
    const float* x     = (const float*)d_in[0];
    const float* w_qkv = (const float*)d_in[1];
    const float* b_qkv = (const float*)d_in[2];
    const float* w_out = (const float*)d_in[3];
    const float* b_out = (const float*)d_in[4];
    float* out = (float*)d_out;

    gemm_qkv<<<dim3(QKV_N / 128, MROWS / 128), 256>>>(x, w_qkv, b_qkv);
    convert_split<<<dim3(SEQ / 64, BH), 256>>>();
    attn_mma<<<dim3(SEQ / 64, BH), 128>>>();
    gemm_out<<<dim3(DIM / 128, MROWS / 128), 256>>>(w_out, b_out, out);
}

// round 6
// speedup vs baseline: 4.3793x; 1.4586x over previous
#include <cuda_runtime.h>
#include <cuda_bf16.h>

#define BATCH 2
#define HEADS 16
#define SEQ   2048
#define DIM   1024
#define HD    64
#define QKV_N (3*DIM)
#define MROWS (BATCH*SEQ)   // 4096
#define BH    (BATCH*HEADS) // 32

// ---------------- scratch (no allocations allowed) ----------------
__device__ __align__(16) __nv_bfloat16 g_xh[MROWS*DIM], g_xl[MROWS*DIM];
__device__ __align__(16) __nv_bfloat16 g_wqh[QKV_N*DIM], g_wql[QKV_N*DIM]; // W^T [n][k]
__device__ __align__(16) __nv_bfloat16 g_woh[DIM*DIM],   g_wol[DIM*DIM];   // W^T [n][k]
__device__ __align__(16) __nv_bfloat16 g_Qh[BH*SEQ*HD], g_Ql[BH*SEQ*HD];
__device__ __align__(16) __nv_bfloat16 g_Kh[BH*SEQ*HD], g_Kl[BH*SEQ*HD];
__device__ __align__(16) float         g_V[BH*SEQ*HD];
__device__ __align__(16) __nv_bfloat16 g_Vth[BH*HD*SEQ], g_Vtl[BH*HD*SEQ]; // [bh][hd][n]
__device__ __align__(16) __nv_bfloat16 g_Ah[MROWS*DIM], g_Al[MROWS*DIM];   // attn out [B,N,D]

// ---------------- helpers ----------------
__device__ __forceinline__ void mma16816(float* c,
    unsigned a0, unsigned a1, unsigned a2, unsigned a3,
    unsigned b0, unsigned b1)
{
    asm volatile(
        "mma.sync.aligned.m16n8k16.row.col.f32.bf16.bf16.f32 "
        "{%0,%1,%2,%3}, {%4,%5,%6,%7}, {%8,%9}, {%0,%1,%2,%3};"
        : "+f"(c[0]), "+f"(c[1]), "+f"(c[2]), "+f"(c[3])
        : "r"(a0), "r"(a1), "r"(a2), "r"(a3), "r"(b0), "r"(b1));
}

__device__ __forceinline__ void bsplit2(float x, float y,
                                        unsigned& hi, unsigned& lo)
{
    __nv_bfloat162 h2, l2;
    h2.x = __float2bfloat16(x);
    h2.y = __float2bfloat16(y);
    l2.x = __float2bfloat16(x - __bfloat162float(h2.x));
    l2.y = __float2bfloat16(y - __bfloat162float(h2.y));
    hi = *reinterpret_cast<unsigned*>(&h2);
    lo = *reinterpret_cast<unsigned*>(&l2);
}

__device__ __forceinline__ void bsplit2v(float x, float y,
                                         __nv_bfloat162& h2, __nv_bfloat162& l2)
{
    h2.x = __float2bfloat16(x);
    h2.y = __float2bfloat16(y);
    l2.x = __float2bfloat16(x - __bfloat162float(h2.x));
    l2.y = __float2bfloat16(y - __bfloat162float(h2.y));
}

// ---------------- pre-pass converts ----------------
__global__ __launch_bounds__(256) void split_x(const float* __restrict__ x)
{
    int i = blockIdx.x * 256 + threadIdx.x;        // float4 index
    float4 v = ((const float4*)x)[i];
    unsigned h0, l0, h1, l1;
    bsplit2(v.x, v.y, h0, l0);
    bsplit2(v.z, v.w, h1, l1);
    uint2 H = make_uint2(h0, h1), L = make_uint2(l0, l1);
    ((uint2*)g_xh)[i] = H;
    ((uint2*)g_xl)[i] = L;
}

// W [K=DIM][N] fp32 -> W^T [N][DIM] bf16 hi/lo. which: 0=w_qkv, 1=w_out
__global__ __launch_bounds__(256) void tsplit_w(const float* __restrict__ W,
                                                int N, int which)
{
    __shared__ float t[32][33];
    __nv_bfloat16* Th = which ? g_woh : g_wqh;
    __nv_bfloat16* Tl = which ? g_wol : g_wql;
    const int n0 = blockIdx.x * 32, k0 = blockIdx.y * 32;
    const int tx = threadIdx.x & 31, ty = threadIdx.x >> 5;
    for (int r = ty; r < 32; r += 8)
        t[r][tx] = W[(size_t)(k0 + r) * N + n0 + tx];
    __syncthreads();
    for (int r = ty; r < 32; r += 8) {
        float v = t[tx][r];                         // = W[k0+tx][n0+r]
        __nv_bfloat16 h = __float2bfloat16(v);
        size_t o = (size_t)(n0 + r) * DIM + k0 + tx;
        Th[o] = h;
        Tl[o] = __float2bfloat16(v - __bfloat162float(h));
    }
}

// ---------------- 3-term split-bf16 GEMM core (128x128 block, BK=32) -------
// A [M][K] row-major hi/lo; B = W^T [N][K] hi/lo. 256 thr = 8 warps (4m x 2n),
// warp tile 32m x 64n. acc[mt][nt][4].
__device__ __forceinline__ void gemm_core128(
    const __nv_bfloat16* __restrict__ Ahg, const __nv_bfloat16* __restrict__ Alg,
    const __nv_bfloat16* __restrict__ Bhg, const __nv_bfloat16* __restrict__ Blg,
    int K, int row0, int col0, float acc[2][8][4])
{
    __shared__ __align__(16) __nv_bfloat16 Ash[128][40], Asl[128][40];
    __shared__ __align__(16) __nv_bfloat16 Bsh[128][40], Bsl[128][40];

    const int tid = threadIdx.x;
    const int warp = tid >> 5, lane = tid & 31;
    const int g = lane >> 2, tig = lane & 3;
    const int wm = (warp & 3) * 32, wn = (warp >> 2) * 64;

    for (int k0 = 0; k0 < K; k0 += 32) {
        __syncthreads();
#pragma unroll
        for (int c = 0; c < 2; c++) {
            int i = tid + c * 256;                  // 512 float4 per half
            int r = i >> 2, sg = (i & 3) * 8;
            size_t ga = (size_t)(row0 + r) * K + k0 + sg;
            *(float4*)&Ash[r][sg] = *(const float4*)&Ahg[ga];
            *(float4*)&Asl[r][sg] = *(const float4*)&Alg[ga];
            size_t gb = (size_t)(col0 + r) * K + k0 + sg;
            *(float4*)&Bsh[r][sg] = *(const float4*)&Bhg[gb];
            *(float4*)&Bsl[r][sg] = *(const float4*)&Blg[gb];
        }
        __syncthreads();

#pragma unroll
        for (int kc = 0; kc < 2; kc++) {
            const int c0 = kc * 16 + 2 * tig;
            unsigned afh[2][4], afl[2][4];
#pragma unroll
            for (int mt = 0; mt < 2; mt++) {
                int m0 = wm + mt * 16;
                afh[mt][0] = *(const unsigned*)&Ash[m0 + g][c0];
                afh[mt][1] = *(const unsigned*)&Ash[m0 + g + 8][c0];
                afh[mt][2] = *(const unsigned*)&Ash[m0 + g][c0 + 8];
                afh[mt][3] = *(const unsigned*)&Ash[m0 + g + 8][c0 + 8];
                afl[mt][0] = *(const unsigned*)&Asl[m0 + g][c0];
                afl[mt][1] = *(const unsigned*)&Asl[m0 + g + 8][c0];
                afl[mt][2] = *(const unsigned*)&Asl[m0 + g][c0 + 8];
                afl[mt][3] = *(const unsigned*)&Asl[m0 + g + 8][c0 + 8];
            }
#pragma unroll
            for (int nt = 0; nt < 8; nt++) {
                int nr = wn + nt * 8 + g;
                unsigned bh0 = *(const unsigned*)&Bsh[nr][c0];
                unsigned bh1 = *(const unsigned*)&Bsh[nr][c0 + 8];
                unsigned bl0 = *(const unsigned*)&Bsl[nr][c0];
                unsigned bl1 = *(const unsigned*)&Bsl[nr][c0 + 8];
#pragma unroll
                for (int mt = 0; mt < 2; mt++) {
                    mma16816(acc[mt][nt], afh[mt][0], afh[mt][1], afh[mt][2], afh[mt][3], bh0, bh1);
                    mma16816(acc[mt][nt], afh[mt][0], afh[mt][1], afh[mt][2], afh[mt][3], bl0, bl1);
                    mma16816(acc[mt][nt], afl[mt][0], afl[mt][1], afl[mt][2], afl[mt][3], bh0, bh1);
                }
            }
        }
    }
}

// ---------------- GEMM 1: qkv, epilogue scatters split Q/K + fp32 V --------
__global__ __launch_bounds__(256) void gemm_qkv_mma(const float* __restrict__ bias)
{
    float acc[2][8][4];
#pragma unroll
    for (int mt = 0; mt < 2; mt++)
#pragma unroll
        for (int nt = 0; nt < 8; nt++)
#pragma unroll
            for (int e = 0; e < 4; e++) acc[mt][nt][e] = 0.f;

    const int row0 = blockIdx.y * 128, col0 = blockIdx.x * 128;
    gemm_core128(g_xh, g_xl, g_wqh, g_wql, DIM, row0, col0, acc);

    const int lane = threadIdx.x & 31, warp = threadIdx.x >> 5;
    const int g = lane >> 2, tig = lane & 3;
    const int wm = (warp & 3) * 32, wn = (warp >> 2) * 64;

#pragma unroll
    for (int nt = 0; nt < 8; nt++) {
        int cb = col0 + wn + nt * 8 + 2 * tig;
        float bv0 = bias[cb], bv1 = bias[cb + 1];
        int s = cb >> 10, rr = cb & (DIM - 1);
        int h = rr >> 6, d = rr & (HD - 1);
#pragma unroll
        for (int mt = 0; mt < 2; mt++) {
#pragma unroll
            for (int half = 0; half < 2; half++) {
                int r = row0 + wm + mt * 16 + g + 8 * half;
                float v0 = acc[mt][nt][2 * half + 0] + bv0;
                float v1 = acc[mt][nt][2 * half + 1] + bv1;
                int b_ = r >> 11, n = r & (SEQ - 1);
                size_t idx = (((size_t)(b_ * HEADS + h) * SEQ) + n) * HD + d;
                if (s == 0) {
                    __nv_bfloat162 hh, ll;
                    bsplit2v(v0 * 0.125f, v1 * 0.125f, hh, ll);
                    *(__nv_bfloat162*)&g_Qh[idx] = hh;
                    *(__nv_bfloat162*)&g_Ql[idx] = ll;
                } else if (s == 1) {
                    __nv_bfloat162 hh, ll;
                    bsplit2v(v0, v1, hh, ll);
                    *(__nv_bfloat162*)&g_Kh[idx] = hh;
                    *(__nv_bfloat162*)&g_Kl[idx] = ll;
                } else {
                    *(float2*)&g_V[idx] = make_float2(v0, v1);
                }
            }
        }
    }
}

// ---------------- V transpose + split: [bh][n][hd] fp32 -> [bh][hd][n] -----
__global__ __launch_bounds__(256) void convert_v()
{
    __shared__ float vt[64][65];
    const int bh = blockIdx.y;
    const int s0 = blockIdx.x * 64;
    const int tid = threadIdx.x;
    const size_t base = ((size_t)bh * SEQ + s0) * HD;

    for (int i = tid; i < 64 * HD; i += 256) {
        int s = i >> 6, d = i & 63;
        vt[s][d] = g_V[base + i];
    }
    __syncthreads();
    for (int i = tid; i < 64 * HD; i += 256) {
        int d = i >> 6, s = i & 63;
        float v = vt[s][d];
        __nv_bfloat16 vh = __float2bfloat16(v);
        size_t o = ((size_t)bh * HD + d) * SEQ + s0 + s;
        g_Vth[o] = vh;
        g_Vtl[o] = __float2bfloat16(v - __bfloat162float(vh));
    }
}

// ---------------- tensor-core flash attention (R5, split-bf16 output) ------
#define KSP 72
#define VSP 40

__global__ __launch_bounds__(128) void attn_mma()
{
    __shared__ __nv_bfloat16 Ksh[32][KSP];
    __shared__ __nv_bfloat16 Ksl[32][KSP];
    __shared__ __nv_bfloat16 Vsh[HD][VSP];
    __shared__ __nv_bfloat16 Vsl[HD][VSP];

    const int tid  = threadIdx.x;
    const int warp = tid >> 5;
    const int lane = tid & 31;
    const int g    = lane >> 2;
    const int tig  = lane & 3;

    const int bh = blockIdx.y;
    const int q0 = blockIdx.x * 64;
    const int qbase = q0 + warp * 16;

    unsigned aqh[4][4], aql[4][4];
    {
        const __nv_bfloat16* Qh = g_Qh + ((size_t)bh * SEQ + qbase) * HD;
        const __nv_bfloat16* Ql = g_Ql + ((size_t)bh * SEQ + qbase) * HD;
#pragma unroll
        for (int kc = 0; kc < 4; kc++) {
            int d0 = 16 * kc + 2 * tig;
            aqh[kc][0] = *(const unsigned*)&Qh[(size_t)g * HD + d0];
            aqh[kc][1] = *(const unsigned*)&Qh[(size_t)(g + 8) * HD + d0];
            aqh[kc][2] = *(const unsigned*)&Qh[(size_t)g * HD + d0 + 8];
            aqh[kc][3] = *(const unsigned*)&Qh[(size_t)(g + 8) * HD + d0 + 8];
            aql[kc][0] = *(const unsigned*)&Ql[(size_t)g * HD + d0];
            aql[kc][1] = *(const unsigned*)&Ql[(size_t)(g + 8) * HD + d0];
            aql[kc][2] = *(const unsigned*)&Ql[(size_t)g * HD + d0 + 8];
            aql[kc][3] = *(const unsigned*)&Ql[(size_t)(g + 8) * HD + d0 + 8];
        }
    }

    float oacc[8][4];
#pragma unroll
    for (int dt = 0; dt < 8; dt++)
#pragma unroll
        for (int e = 0; e < 4; e++) oacc[dt][e] = 0.f;
    float m0 = -1e30f, m1 = -1e30f, l0 = 0.f, l1 = 0.f;

    const __nv_bfloat16* Khg = g_Kh + (size_t)bh * SEQ * HD;
    const __nv_bfloat16* Klg = g_Kl + (size_t)bh * SEQ * HD;
    const __nv_bfloat16* Vthg = g_Vth + (size_t)bh * HD * SEQ;
    const __nv_bfloat16* Vtlg = g_Vtl + (size_t)bh * HD * SEQ;

    for (int kt = 0; kt < SEQ; kt += 32) {
        __syncthreads();
#pragma unroll
        for (int c = 0; c < 2; c++) {
            int i = tid + c * 128;
            int r = i >> 3, seg = i & 7;
            const size_t ko = (size_t)(kt + r) * HD + seg * 8;
            *(float4*)&Ksh[r][seg * 8] = *(const float4*)&Khg[ko];
            *(float4*)&Ksl[r][seg * 8] = *(const float4*)&Klg[ko];
            int rv = i >> 2, sv = i & 3;
            const size_t vo = (size_t)rv * SEQ + kt + sv * 8;
            *(float4*)&Vsh[rv][sv * 8] = *(const float4*)&Vthg[vo];
            *(float4*)&Vsl[rv][sv * 8] = *(const float4*)&Vtlg[vo];
        }
        __syncthreads();

        float sacc[4][4];
#pragma unroll
        for (int j = 0; j < 4; j++) {
#pragma unroll
            for (int e = 0; e < 4; e++) sacc[j][e] = 0.f;
            int key = 8 * j + g;
#pragma unroll
            for (int kc = 0; kc < 4; kc++) {
                int d0 = 16 * kc + 2 * tig;
                unsigned bh0 = *(const unsigned*)&Ksh[key][d0];
                unsigned bh1 = *(const unsigned*)&Ksh[key][d0 + 8];
                unsigned bl0 = *(const unsigned*)&Ksl[key][d0];
                unsigned bl1 = *(const unsigned*)&Ksl[key][d0 + 8];
                mma16816(sacc[j], aqh[kc][0], aqh[kc][1], aqh[kc][2], aqh[kc][3], bh0, bh1);
                mma16816(sacc[j], aqh[kc][0], aqh[kc][1], aqh[kc][2], aqh[kc][3], bl0, bl1);
                mma16816(sacc[j], aql[kc][0], aql[kc][1], aql[kc][2], aql[kc][3], bh0, bh1);
            }
        }

        float r0 = -1e30f, r1 = -1e30f;
#pragma unroll
        for (int j = 0; j < 4; j++) {
            r0 = fmaxf(r0, fmaxf(sacc[j][0], sacc[j][1]));
            r1 = fmaxf(r1, fmaxf(sacc[j][2], sacc[j][3]));
        }
        r0 = fmaxf(r0, __shfl_xor_sync(0xFFFFFFFFu, r0, 1));
        r0 = fmaxf(r0, __shfl_xor_sync(0xFFFFFFFFu, r0, 2));
        r1 = fmaxf(r1, __shfl_xor_sync(0xFFFFFFFFu, r1, 1));
        r1 = fmaxf(r1, __shfl_xor_sync(0xFFFFFFFFu, r1, 2));
        float mn0 = fmaxf(m0, r0), mn1 = fmaxf(m1, r1);
        float corr0 = __expf(m0 - mn0), corr1 = __expf(m1 - mn1);
        m0 = mn0; m1 = mn1;

        float ls0 = 0.f, ls1 = 0.f;
#pragma unroll
        for (int j = 0; j < 4; j++) {
            sacc[j][0] = __expf(sacc[j][0] - mn0);
            sacc[j][1] = __expf(sacc[j][1] - mn0);
            sacc[j][2] = __expf(sacc[j][2] - mn1);
            sacc[j][3] = __expf(sacc[j][3] - mn1);
            ls0 += sacc[j][0] + sacc[j][1];
            ls1 += sacc[j][2] + sacc[j][3];
        }
        ls0 += __shfl_xor_sync(0xFFFFFFFFu, ls0, 1);
        ls0 += __shfl_xor_sync(0xFFFFFFFFu, ls0, 2);
        ls1 += __shfl_xor_sync(0xFFFFFFFFu, ls1, 1);
        ls1 += __shfl_xor_sync(0xFFFFFFFFu, ls1, 2);
        l0 = l0 * corr0 + ls0;
        l1 = l1 * corr1 + ls1;

#pragma unroll
        for (int dt = 0; dt < 8; dt++) {
            oacc[dt][0] *= corr0; oacc[dt][1] *= corr0;
            oacc[dt][2] *= corr1; oacc[dt][3] *= corr1;
        }

        unsigned aph[2][4], apl[2][4];
#pragma unroll
        for (int kc2 = 0; kc2 < 2; kc2++) {
            int j0 = 2 * kc2, j1 = 2 * kc2 + 1;
            bsplit2(sacc[j0][0], sacc[j0][1], aph[kc2][0], apl[kc2][0]);
            bsplit2(sacc[j0][2], sacc[j0][3], aph[kc2][1], apl[kc2][1]);
            bsplit2(sacc[j1][0], sacc[j1][1], aph[kc2][2], apl[kc2][2]);
            bsplit2(sacc[j1][2], sacc[j1][3], aph[kc2][3], apl[kc2][3]);
        }

#pragma unroll
        for (int dt = 0; dt < 8; dt++) {
            int drow = 8 * dt + g;
#pragma unroll
            for (int kc2 = 0; kc2 < 2; kc2++) {
                int k0c = 16 * kc2 + 2 * tig;
                unsigned bh0 = *(const unsigned*)&Vsh[drow][k0c];
                unsigned bh1 = *(const unsigned*)&Vsh[drow][k0c + 8];
                unsigned bl0 = *(const unsigned*)&Vsl[drow][k0c];
                unsigned bl1 = *(const unsigned*)&Vsl[drow][k0c + 8];
                mma16816(oacc[dt], aph[kc2][0], aph[kc2][1], aph[kc2][2], aph[kc2][3], bh0, bh1);
                mma16816(oacc[dt], aph[kc2][0], aph[kc2][1], aph[kc2][2], aph[kc2][3], bl0, bl1);
                mma16816(oacc[dt], apl[kc2][0], apl[kc2][1], apl[kc2][2], apl[kc2][3], bh0, bh1);
            }
        }
    }

    // epilogue: normalize, split to bf16 hi/lo attn output [B,N,D]
    const int b_ = bh >> 4, h = bh & 15;
    const float inv0 = 1.f / l0, inv1 = 1.f / l1;
    const int qg0 = qbase + g, qg1 = qbase + g + 8;
    const size_t o0 = ((size_t)(b_ * SEQ + qg0)) * DIM + h * HD;
    const size_t o1 = ((size_t)(b_ * SEQ + qg1)) * DIM + h * HD;
#pragma unroll
    for (int dt = 0; dt < 8; dt++) {
        int d = 8 * dt + 2 * tig;
        __nv_bfloat162 hh, ll;
        bsplit2v(oacc[dt][0] * inv0, oacc[dt][1] * inv0, hh, ll);
        *(__nv_bfloat162*)&g_Ah[o0 + d] = hh;
        *(__nv_bfloat162*)&g_Al[o0 + d] = ll;
        bsplit2v(oacc[dt][2] * inv1, oacc[dt][3] * inv1, hh, ll);
        *(__nv_bfloat162*)&g_Ah[o1 + d] = hh;
        *(__nv_bfloat162*)&g_Al[o1 + d] = ll;
    }
}

// ---------------- GEMM 2: out = attn @ w_out + b_out ----------------------
__global__ __launch_bounds__(256) void gemm_out_mma(const float* __restrict__ bias,
                                                    float* __restrict__ out)
{
    float acc[2][8][4];
#pragma unroll
    for (int mt = 0; mt < 2; mt++)
#pragma unroll
        for (int nt = 0; nt < 8; nt++)
#pragma unroll
            for (int e = 0; e < 4; e++) acc[mt][nt][e] = 0.f;

    const int row0 = blockIdx.y * 128, col0 = blockIdx.x * 128;
    gemm_core128(g_Ah, g_Al, g_woh, g_wol, DIM, row0, col0, acc);

    const int lane = threadIdx.x & 31, warp = threadIdx.x >> 5;
    const int g = lane >> 2, tig = lane & 3;
    const int wm = (warp & 3) * 32, wn = (warp >> 2) * 64;

#pragma unroll
    for (int nt = 0; nt < 8; nt++) {
        int cb = col0 + wn + nt * 8 + 2 * tig;
        float bv0 = bias[cb], bv1 = bias[cb + 1];
#pragma unroll
        for (int mt = 0; mt < 2; mt++) {
            int r = row0 + wm + mt * 16 + g;
            *(float2*)&out[(size_t)r * DIM + cb] =
                make_float2(acc[mt][nt][0] + bv0, acc[mt][nt][1] + bv1);
            *(float2*)&out[(size_t)(r + 8) * DIM + cb] =
                make_float2(acc[mt][nt][2] + bv0, acc[mt][nt][3] + bv1);
        }
    }
}

extern "C" void kernel_launch(void* const* d_in, const int* in_sizes, int n_in,
                              void* d_out, int out_size)
{
    (void)in_sizes; (void)n_in; (void)out_size;
    const float* x     = (const float*)d_in[0];
    const float* w_qkv = (const float*)d_in[1];
    const float* b_qkv = (const float*)d_in[2];
    const float* w_out = (const float*)d_in[3];
    const float* b_out = (const float*)d_in[4];
    float* out = (float*)d_out;

    split_x<<<MROWS * DIM / 1024, 256>>>(x);
    tsplit_w<<<dim3(QKV_N / 32, DIM / 32), 256>>>(w_qkv, QKV_N, 0);
    tsplit_w<<<dim3(DIM / 32, DIM / 32), 256>>>(w_out, DIM, 1);
    gemm_qkv_mma<<<dim3(QKV_N / 128, MROWS / 128), 256>>>(b_qkv);
    convert_v<<<dim3(SEQ / 64, BH), 256>>>();
    attn_mma<<<dim3(SEQ / 64, BH), 128>>>();
    gemm_out_mma<<<dim3(DIM / 128, MROWS / 128), 256>>>(b_out, out);
}

// round 7
// speedup vs baseline: 5.4072x; 1.2347x over previous
#include <cuda_runtime.h>
#include <cuda_bf16.h>

#define BATCH 2
#define HEADS 16
#define SEQ   2048
#define DIM   1024
#define HD    64
#define QKV_N (3*DIM)
#define MROWS (BATCH*SEQ)   // 4096
#define BH    (BATCH*HEADS) // 32

// ---------------- scratch (no allocations allowed) ----------------
__device__ __align__(16) __nv_bfloat16 g_xh[MROWS*DIM], g_xl[MROWS*DIM];
__device__ __align__(16) __nv_bfloat16 g_wqh[QKV_N*DIM], g_wql[QKV_N*DIM]; // W^T [n][k]
__device__ __align__(16) __nv_bfloat16 g_woh[DIM*DIM],   g_wol[DIM*DIM];   // W^T [n][k]
__device__ __align__(16) __nv_bfloat16 g_Qh[BH*SEQ*HD], g_Ql[BH*SEQ*HD];
__device__ __align__(16) __nv_bfloat16 g_Kh[BH*SEQ*HD], g_Kl[BH*SEQ*HD];
__device__ __align__(16) float         g_V[BH*SEQ*HD];
__device__ __align__(16) __nv_bfloat16 g_Vth[BH*HD*SEQ], g_Vtl[BH*HD*SEQ]; // [bh][hd][n]
__device__ __align__(16) __nv_bfloat16 g_Ah[MROWS*DIM], g_Al[MROWS*DIM];   // attn out [B,N,D]

// ---------------- helpers ----------------
__device__ __forceinline__ void mma16816(float* c,
    unsigned a0, unsigned a1, unsigned a2, unsigned a3,
    unsigned b0, unsigned b1)
{
    asm volatile(
        "mma.sync.aligned.m16n8k16.row.col.f32.bf16.bf16.f32 "
        "{%0,%1,%2,%3}, {%4,%5,%6,%7}, {%8,%9}, {%0,%1,%2,%3};"
        : "+f"(c[0]), "+f"(c[1]), "+f"(c[2]), "+f"(c[3])
        : "r"(a0), "r"(a1), "r"(a2), "r"(a3), "r"(b0), "r"(b1));
}

__device__ __forceinline__ void bsplit2(float x, float y,
                                        unsigned& hi, unsigned& lo)
{
    __nv_bfloat162 h2, l2;
    h2.x = __float2bfloat16(x);
    h2.y = __float2bfloat16(y);
    l2.x = __float2bfloat16(x - __bfloat162float(h2.x));
    l2.y = __float2bfloat16(y - __bfloat162float(h2.y));
    hi = *reinterpret_cast<unsigned*>(&h2);
    lo = *reinterpret_cast<unsigned*>(&l2);
}

__device__ __forceinline__ void bsplit2v(float x, float y,
                                         __nv_bfloat162& h2, __nv_bfloat162& l2)
{
    h2.x = __float2bfloat16(x);
    h2.y = __float2bfloat16(y);
    l2.x = __float2bfloat16(x - __bfloat162float(h2.x));
    l2.y = __float2bfloat16(y - __bfloat162float(h2.y));
}

__device__ __forceinline__ void cpa16(void* s, const void* g)
{
    unsigned sa = (unsigned)__cvta_generic_to_shared(s);
    asm volatile("cp.async.cg.shared.global [%0], [%1], 16;" :: "r"(sa), "l"(g));
}
#define CP_COMMIT() asm volatile("cp.async.commit_group;" ::: "memory")
#define CP_WAIT1()  asm volatile("cp.async.wait_group 1;" ::: "memory")
#define CP_WAIT0()  asm volatile("cp.async.wait_group 0;" ::: "memory")

// ---------------- pre-pass converts ----------------
__global__ __launch_bounds__(256) void split_x(const float* __restrict__ x)
{
    int i = blockIdx.x * 256 + threadIdx.x;        // float4 index
    float4 v = ((const float4*)x)[i];
    unsigned h0, l0, h1, l1;
    bsplit2(v.x, v.y, h0, l0);
    bsplit2(v.z, v.w, h1, l1);
    ((uint2*)g_xh)[i] = make_uint2(h0, h1);
    ((uint2*)g_xl)[i] = make_uint2(l0, l1);
}

__global__ __launch_bounds__(256) void tsplit_w(const float* __restrict__ W,
                                                int N, int which)
{
    __shared__ float t[32][33];
    __nv_bfloat16* Th = which ? g_woh : g_wqh;
    __nv_bfloat16* Tl = which ? g_wol : g_wql;
    const int n0 = blockIdx.x * 32, k0 = blockIdx.y * 32;
    const int tx = threadIdx.x & 31, ty = threadIdx.x >> 5;
    for (int r = ty; r < 32; r += 8)
        t[r][tx] = W[(size_t)(k0 + r) * N + n0 + tx];
    __syncthreads();
    for (int r = ty; r < 32; r += 8) {
        float v = t[tx][r];
        __nv_bfloat16 h = __float2bfloat16(v);
        size_t o = (size_t)(n0 + r) * DIM + k0 + tx;
        Th[o] = h;
        Tl[o] = __float2bfloat16(v - __bfloat162float(h));
    }
}

// ---------------- pipelined 3-term split-bf16 GEMM core --------------------
// Dynamic smem: 2 stages x 4 arrays (Ah,Al,Bh,Bl) x 128x40 bf16 = 81920 B.
#define GPAD 40
#define GST  (128*GPAD)
extern __shared__ __nv_bfloat16 dynsmem[];

#define GEMM_LOAD_STAGE(k0, st)                                               \
    do {                                                                      \
        _Pragma("unroll")                                                     \
        for (int c = 0; c < 2; c++) {                                         \
            int i = tid + c * 256;                                            \
            int r = i >> 2, sg = (i & 3) * 8;                                 \
            size_t ga = (size_t)(row0 + r) * K + (k0) + sg;                   \
            size_t gb = (size_t)(col0 + r) * K + (k0) + sg;                   \
            cpa16(dynsmem + ((st) * 4 + 0) * GST + r * GPAD + sg, Ahg + ga);  \
            cpa16(dynsmem + ((st) * 4 + 1) * GST + r * GPAD + sg, Alg + ga);  \
            cpa16(dynsmem + ((st) * 4 + 2) * GST + r * GPAD + sg, Bhg + gb);  \
            cpa16(dynsmem + ((st) * 4 + 3) * GST + r * GPAD + sg, Blg + gb);  \
        }                                                                     \
        CP_COMMIT();                                                          \
    } while (0)

__device__ __forceinline__ void gemm_core128(
    const __nv_bfloat16* __restrict__ Ahg, const __nv_bfloat16* __restrict__ Alg,
    const __nv_bfloat16* __restrict__ Bhg, const __nv_bfloat16* __restrict__ Blg,
    int K, int row0, int col0, float acc[2][8][4])
{
    const int tid = threadIdx.x;
    const int warp = tid >> 5, lane = tid & 31;
    const int g = lane >> 2, tig = lane & 3;
    const int wm = (warp & 3) * 32, wn = (warp >> 2) * 64;

    GEMM_LOAD_STAGE(0, 0);
    int p = 0;
    for (int k0 = 0; k0 < K; k0 += 32) {
        if (k0 + 32 < K) {
            GEMM_LOAD_STAGE(k0 + 32, p ^ 1);
            CP_WAIT1();
        } else {
            CP_WAIT0();
        }
        __syncthreads();

        const __nv_bfloat16* ASH = dynsmem + (p * 4 + 0) * GST;
        const __nv_bfloat16* ASL = dynsmem + (p * 4 + 1) * GST;
        const __nv_bfloat16* BSH = dynsmem + (p * 4 + 2) * GST;
        const __nv_bfloat16* BSL = dynsmem + (p * 4 + 3) * GST;

#pragma unroll
        for (int kc = 0; kc < 2; kc++) {
            const int c0 = kc * 16 + 2 * tig;
            unsigned afh[2][4], afl[2][4];
#pragma unroll
            for (int mt = 0; mt < 2; mt++) {
                int m0 = wm + mt * 16;
                afh[mt][0] = *(const unsigned*)&ASH[(m0 + g) * GPAD + c0];
                afh[mt][1] = *(const unsigned*)&ASH[(m0 + g + 8) * GPAD + c0];
                afh[mt][2] = *(const unsigned*)&ASH[(m0 + g) * GPAD + c0 + 8];
                afh[mt][3] = *(const unsigned*)&ASH[(m0 + g + 8) * GPAD + c0 + 8];
                afl[mt][0] = *(const unsigned*)&ASL[(m0 + g) * GPAD + c0];
                afl[mt][1] = *(const unsigned*)&ASL[(m0 + g + 8) * GPAD + c0];
                afl[mt][2] = *(const unsigned*)&ASL[(m0 + g) * GPAD + c0 + 8];
                afl[mt][3] = *(const unsigned*)&ASL[(m0 + g + 8) * GPAD + c0 + 8];
            }
#pragma unroll
            for (int nt = 0; nt < 8; nt++) {
                int nr = wn + nt * 8 + g;
                unsigned bh0 = *(const unsigned*)&BSH[nr * GPAD + c0];
                unsigned bh1 = *(const unsigned*)&BSH[nr * GPAD + c0 + 8];
                unsigned bl0 = *(const unsigned*)&BSL[nr * GPAD + c0];
                unsigned bl1 = *(const unsigned*)&BSL[nr * GPAD + c0 + 8];
#pragma unroll
                for (int mt = 0; mt < 2; mt++) {
                    mma16816(acc[mt][nt], afh[mt][0], afh[mt][1], afh[mt][2], afh[mt][3], bh0, bh1);
                    mma16816(acc[mt][nt], afh[mt][0], afh[mt][1], afh[mt][2], afh[mt][3], bl0, bl1);
                    mma16816(acc[mt][nt], afl[mt][0], afl[mt][1], afl[mt][2], afl[mt][3], bh0, bh1);
                }
            }
        }
        __syncthreads();
        p ^= 1;
    }
}

// ---------------- GEMM 1: qkv, epilogue scatters split Q/K + fp32 V --------
__global__ __launch_bounds__(256) void gemm_qkv_mma(const float* __restrict__ bias)
{
    float acc[2][8][4];
#pragma unroll
    for (int mt = 0; mt < 2; mt++)
#pragma unroll
        for (int nt = 0; nt < 8; nt++)
#pragma unroll
            for (int e = 0; e < 4; e++) acc[mt][nt][e] = 0.f;

    const int row0 = blockIdx.y * 128, col0 = blockIdx.x * 128;
    gemm_core128(g_xh, g_xl, g_wqh, g_wql, DIM, row0, col0, acc);

    const int lane = threadIdx.x & 31, warp = threadIdx.x >> 5;
    const int g = lane >> 2, tig = lane & 3;
    const int wm = (warp & 3) * 32, wn = (warp >> 2) * 64;

#pragma unroll
    for (int nt = 0; nt < 8; nt++) {
        int cb = col0 + wn + nt * 8 + 2 * tig;
        float bv0 = bias[cb], bv1 = bias[cb + 1];
        int s = cb >> 10, rr = cb & (DIM - 1);
        int h = rr >> 6, d = rr & (HD - 1);
#pragma unroll
        for (int mt = 0; mt < 2; mt++) {
#pragma unroll
            for (int half = 0; half < 2; half++) {
                int r = row0 + wm + mt * 16 + g + 8 * half;
                float v0 = acc[mt][nt][2 * half + 0] + bv0;
                float v1 = acc[mt][nt][2 * half + 1] + bv1;
                int b_ = r >> 11, n = r & (SEQ - 1);
                size_t idx = (((size_t)(b_ * HEADS + h) * SEQ) + n) * HD + d;
                if (s == 0) {
                    __nv_bfloat162 hh, ll;
                    bsplit2v(v0 * 0.125f, v1 * 0.125f, hh, ll);
                    *(__nv_bfloat162*)&g_Qh[idx] = hh;
                    *(__nv_bfloat162*)&g_Ql[idx] = ll;
                } else if (s == 1) {
                    __nv_bfloat162 hh, ll;
                    bsplit2v(v0, v1, hh, ll);
                    *(__nv_bfloat162*)&g_Kh[idx] = hh;
                    *(__nv_bfloat162*)&g_Kl[idx] = ll;
                } else {
                    *(float2*)&g_V[idx] = make_float2(v0, v1);
                }
            }
        }
    }
}

// ---------------- V transpose + split ----------------
__global__ __launch_bounds__(256) void convert_v()
{
    __shared__ float vt[64][65];
    const int bh = blockIdx.y;
    const int s0 = blockIdx.x * 64;
    const int tid = threadIdx.x;
    const size_t base = ((size_t)bh * SEQ + s0) * HD;

    for (int i = tid; i < 64 * HD; i += 256) {
        int s = i >> 6, d = i & 63;
        vt[s][d] = g_V[base + i];
    }
    __syncthreads();
    for (int i = tid; i < 64 * HD; i += 256) {
        int d = i >> 6, s = i & 63;
        float v = vt[s][d];
        __nv_bfloat16 vh = __float2bfloat16(v);
        size_t o = ((size_t)bh * HD + d) * SEQ + s0 + s;
        g_Vth[o] = vh;
        g_Vtl[o] = __float2bfloat16(v - __bfloat162float(vh));
    }
}

// ---------------- tensor-core flash attention, cp.async pipelined ----------
#define KSP 72
#define VSP 40

#define ATTN_LOAD_STAGE(kt, st)                                               \
    do {                                                                      \
        _Pragma("unroll")                                                     \
        for (int c = 0; c < 2; c++) {                                         \
            int i = tid + c * 128;                                            \
            int r = i >> 3, seg = i & 7;                                      \
            size_t ko = (size_t)((kt) + r) * HD + seg * 8;                    \
            cpa16(&Ksh[st][r][seg * 8], Khg + ko);                            \
            cpa16(&Ksl[st][r][seg * 8], Klg + ko);                            \
            int rv = i >> 2, sv = i & 3;                                      \
            size_t vo = (size_t)rv * SEQ + (kt) + sv * 8;                     \
            cpa16(&Vsh[st][rv][sv * 8], Vthg + vo);                           \
            cpa16(&Vsl[st][rv][sv * 8], Vtlg + vo);                           \
        }                                                                     \
        CP_COMMIT();                                                          \
    } while (0)

__global__ __launch_bounds__(128) void attn_mma()
{
    __shared__ __nv_bfloat16 Ksh[2][32][KSP];
    __shared__ __nv_bfloat16 Ksl[2][32][KSP];
    __shared__ __nv_bfloat16 Vsh[2][HD][VSP];
    __shared__ __nv_bfloat16 Vsl[2][HD][VSP];

    const int tid  = threadIdx.x;
    const int warp = tid >> 5;
    const int lane = tid & 31;
    const int g    = lane >> 2;
    const int tig  = lane & 3;

    const int bh = blockIdx.y;
    const int q0 = blockIdx.x * 64;
    const int qbase = q0 + warp * 16;

    const __nv_bfloat16* Khg = g_Kh + (size_t)bh * SEQ * HD;
    const __nv_bfloat16* Klg = g_Kl + (size_t)bh * SEQ * HD;
    const __nv_bfloat16* Vthg = g_Vth + (size_t)bh * HD * SEQ;
    const __nv_bfloat16* Vtlg = g_Vtl + (size_t)bh * HD * SEQ;

    // Prefetch tile 0 before the (long-latency) Q fragment loads
    ATTN_LOAD_STAGE(0, 0);

    unsigned aqh[4][4], aql[4][4];
    {
        const __nv_bfloat16* Qh = g_Qh + ((size_t)bh * SEQ + qbase) * HD;
        const __nv_bfloat16* Ql = g_Ql + ((size_t)bh * SEQ + qbase) * HD;
#pragma unroll
        for (int kc = 0; kc < 4; kc++) {
            int d0 = 16 * kc + 2 * tig;
            aqh[kc][0] = *(const unsigned*)&Qh[(size_t)g * HD + d0];
            aqh[kc][1] = *(const unsigned*)&Qh[(size_t)(g + 8) * HD + d0];
            aqh[kc][2] = *(const unsigned*)&Qh[(size_t)g * HD + d0 + 8];
            aqh[kc][3] = *(const unsigned*)&Qh[(size_t)(g + 8) * HD + d0 + 8];
            aql[kc][0] = *(const unsigned*)&Ql[(size_t)g * HD + d0];
            aql[kc][1] = *(const unsigned*)&Ql[(size_t)(g + 8) * HD + d0];
            aql[kc][2] = *(const unsigned*)&Ql[(size_t)g * HD + d0 + 8];
            aql[kc][3] = *(const unsigned*)&Ql[(size_t)(g + 8) * HD + d0 + 8];
        }
    }

    float oacc[8][4];
#pragma unroll
    for (int dt = 0; dt < 8; dt++)
#pragma unroll
        for (int e = 0; e < 4; e++) oacc[dt][e] = 0.f;
    float m0 = -1e30f, m1 = -1e30f, l0 = 0.f, l1 = 0.f;

    int p = 0;
    for (int kt = 0; kt < SEQ; kt += 32) {
        if (kt + 32 < SEQ) {
            ATTN_LOAD_STAGE(kt + 32, p ^ 1);
            CP_WAIT1();
        } else {
            CP_WAIT0();
        }
        __syncthreads();

        float sacc[4][4];
#pragma unroll
        for (int j = 0; j < 4; j++) {
#pragma unroll
            for (int e = 0; e < 4; e++) sacc[j][e] = 0.f;
            int key = 8 * j + g;
#pragma unroll
            for (int kc = 0; kc < 4; kc++) {
                int d0 = 16 * kc + 2 * tig;
                unsigned bh0 = *(const unsigned*)&Ksh[p][key][d0];
                unsigned bh1 = *(const unsigned*)&Ksh[p][key][d0 + 8];
                unsigned bl0 = *(const unsigned*)&Ksl[p][key][d0];
                unsigned bl1 = *(const unsigned*)&Ksl[p][key][d0 + 8];
                mma16816(sacc[j], aqh[kc][0], aqh[kc][1], aqh[kc][2], aqh[kc][3], bh0, bh1);
                mma16816(sacc[j], aqh[kc][0], aqh[kc][1], aqh[kc][2], aqh[kc][3], bl0, bl1);
                mma16816(sacc[j], aql[kc][0], aql[kc][1], aql[kc][2], aql[kc][3], bh0, bh1);
            }
        }

        float r0 = -1e30f, r1 = -1e30f;
#pragma unroll
        for (int j = 0; j < 4; j++) {
            r0 = fmaxf(r0, fmaxf(sacc[j][0], sacc[j][1]));
            r1 = fmaxf(r1, fmaxf(sacc[j][2], sacc[j][3]));
        }
        r0 = fmaxf(r0, __shfl_xor_sync(0xFFFFFFFFu, r0, 1));
        r0 = fmaxf(r0, __shfl_xor_sync(0xFFFFFFFFu, r0, 2));
        r1 = fmaxf(r1, __shfl_xor_sync(0xFFFFFFFFu, r1, 1));
        r1 = fmaxf(r1, __shfl_xor_sync(0xFFFFFFFFu, r1, 2));
        float mn0 = fmaxf(m0, r0), mn1 = fmaxf(m1, r1);
        float corr0 = __expf(m0 - mn0), corr1 = __expf(m1 - mn1);
        m0 = mn0; m1 = mn1;

        float ls0 = 0.f, ls1 = 0.f;
#pragma unroll
        for (int j = 0; j < 4; j++) {
            sacc[j][0] = __expf(sacc[j][0] - mn0);
            sacc[j][1] = __expf(sacc[j][1] - mn0);
            sacc[j][2] = __expf(sacc[j][2] - mn1);
            sacc[j][3] = __expf(sacc[j][3] - mn1);
            ls0 += sacc[j][0] + sacc[j][1];
            ls1 += sacc[j][2] + sacc[j][3];
        }
        ls0 += __shfl_xor_sync(0xFFFFFFFFu, ls0, 1);
        ls0 += __shfl_xor_sync(0xFFFFFFFFu, ls0, 2);
        ls1 += __shfl_xor_sync(0xFFFFFFFFu, ls1, 1);
        ls1 += __shfl_xor_sync(0xFFFFFFFFu, ls1, 2);
        l0 = l0 * corr0 + ls0;
        l1 = l1 * corr1 + ls1;

#pragma unroll
        for (int dt = 0; dt < 8; dt++) {
            oacc[dt][0] *= corr0; oacc[dt][1] *= corr0;
            oacc[dt][2] *= corr1; oacc[dt][3] *= corr1;
        }

        unsigned aph[2][4], apl[2][4];
#pragma unroll
        for (int kc2 = 0; kc2 < 2; kc2++) {
            int j0 = 2 * kc2, j1 = 2 * kc2 + 1;
            bsplit2(sacc[j0][0], sacc[j0][1], aph[kc2][0], apl[kc2][0]);
            bsplit2(sacc[j0][2], sacc[j0][3], aph[kc2][1], apl[kc2][1]);
            bsplit2(sacc[j1][0], sacc[j1][1], aph[kc2][2], apl[kc2][2]);
            bsplit2(sacc[j1][2], sacc[j1][3], aph[kc2][3], apl[kc2][3]);
        }

#pragma unroll
        for (int dt = 0; dt < 8; dt++) {
            int drow = 8 * dt + g;
#pragma unroll
            for (int kc2 = 0; kc2 < 2; kc2++) {
                int k0c = 16 * kc2 + 2 * tig;
                unsigned bh0 = *(const unsigned*)&Vsh[p][drow][k0c];
                unsigned bh1 = *(const unsigned*)&Vsh[p][drow][k0c + 8];
                unsigned bl0 = *(const unsigned*)&Vsl[p][drow][k0c];
                unsigned bl1 = *(const unsigned*)&Vsl[p][drow][k0c + 8];
                mma16816(oacc[dt], aph[kc2][0], aph[kc2][1], aph[kc2][2], aph[kc2][3], bh0, bh1);
                mma16816(oacc[dt], aph[kc2][0], aph[kc2][1], aph[kc2][2], aph[kc2][3], bl0, bl1);
                mma16816(oacc[dt], apl[kc2][0], apl[kc2][1], apl[kc2][2], apl[kc2][3], bh0, bh1);
            }
        }
        __syncthreads();
        p ^= 1;
    }

    // epilogue: normalize, split to bf16 hi/lo attn output [B,N,D]
    const int b_ = bh >> 4, h = bh & 15;
    const float inv0 = 1.f / l0, inv1 = 1.f / l1;
    const int qg0 = qbase + g, qg1 = qbase + g + 8;
    const size_t o0 = ((size_t)(b_ * SEQ + qg0)) * DIM + h * HD;
    const size_t o1 = ((size_t)(b_ * SEQ + qg1)) * DIM + h * HD;
#pragma unroll
    for (int dt = 0; dt < 8; dt++) {
        int d = 8 * dt + 2 * tig;
        __nv_bfloat162 hh, ll;
        bsplit2v(oacc[dt][0] * inv0, oacc[dt][1] * inv0, hh, ll);
        *(__nv_bfloat162*)&g_Ah[o0 + d] = hh;
        *(__nv_bfloat162*)&g_Al[o0 + d] = ll;
        bsplit2v(oacc[dt][2] * inv1, oacc[dt][3] * inv1, hh, ll);
        *(__nv_bfloat162*)&g_Ah[o1 + d] = hh;
        *(__nv_bfloat162*)&g_Al[o1 + d] = ll;
    }
}

// ---------------- GEMM 2: out = attn @ w_out + b_out ----------------------
__global__ __launch_bounds__(256) void gemm_out_mma(const float* __restrict__ bias,
                                                    float* __restrict__ out)
{
    float acc[2][8][4];
#pragma unroll
    for (int mt = 0; mt < 2; mt++)
#pragma unroll
        for (int nt = 0; nt < 8; nt++)
#pragma unroll
            for (int e = 0; e < 4; e++) acc[mt][nt][e] = 0.f;

    const int row0 = blockIdx.y * 128, col0 = blockIdx.x * 128;
    gemm_core128(g_Ah, g_Al, g_woh, g_wol, DIM, row0, col0, acc);

    const int lane = threadIdx.x & 31, warp = threadIdx.x >> 5;
    const int g = lane >> 2, tig = lane & 3;
    const int wm = (warp & 3) * 32, wn = (warp >> 2) * 64;

#pragma unroll
    for (int nt = 0; nt < 8; nt++) {
        int cb = col0 + wn + nt * 8 + 2 * tig;
        float bv0 = bias[cb], bv1 = bias[cb + 1];
#pragma unroll
        for (int mt = 0; mt < 2; mt++) {
            int r = row0 + wm + mt * 16 + g;
            *(float2*)&out[(size_t)r * DIM + cb] =
                make_float2(acc[mt][nt][0] + bv0, acc[mt][nt][1] + bv1);
            *(float2*)&out[(size_t)(r + 8) * DIM + cb] =
                make_float2(acc[mt][nt][2] + bv0, acc[mt][nt][3] + bv1);
        }
    }
}

extern "C" void kernel_launch(void* const* d_in, const int* in_sizes, int n_in,
                              void* d_out, int out_size)
{
    (void)in_sizes; (void)n_in; (void)out_size;
    const float* x     = (const float*)d_in[0];
    const float* w_qkv = (const float*)d_in[1];
    const float* b_qkv = (const float*)d_in[2];
    const float* w_out = (const float*)d_in[3];
    const float* b_out = (const float*)d_in[4];
    float* out = (float*)d_out;

    const int GEMM_SMEM = 2 * 4 * GST * (int)sizeof(__nv_bfloat16);  // 81920
    cudaFuncSetAttribute(gemm_qkv_mma,
                         cudaFuncAttributeMaxDynamicSharedMemorySize, GEMM_SMEM);
    cudaFuncSetAttribute(gemm_out_mma,
                         cudaFuncAttributeMaxDynamicSharedMemorySize, GEMM_SMEM);

    split_x<<<MROWS * DIM / 1024, 256>>>(x);
    tsplit_w<<<dim3(QKV_N / 32, DIM / 32), 256>>>(w_qkv, QKV_N, 0);
    tsplit_w<<<dim3(DIM / 32, DIM / 32), 256>>>(w_out, DIM, 1);
    gemm_qkv_mma<<<dim3(QKV_N / 128, MROWS / 128), 256, GEMM_SMEM>>>(b_qkv);
    convert_v<<<dim3(SEQ / 64, BH), 256>>>();
    attn_mma<<<dim3(SEQ / 64, BH), 128>>>();
    gemm_out_mma<<<dim3(DIM / 128, MROWS / 128), 256, GEMM_SMEM>>>(b_out, out);
}

// round 9
// speedup vs baseline: 5.5394x; 1.0245x over previous
#include <cuda_runtime.h>
#include <cuda_bf16.h>

#define BATCH 2
#define HEADS 16
#define SEQ   2048
#define DIM   1024
#define HD    64
#define QKV_N (3*DIM)
#define MROWS (BATCH*SEQ)   // 4096
#define BH    (BATCH*HEADS) // 32

// ---------------- scratch (no allocations allowed) ----------------
__device__ __align__(16) __nv_bfloat16 g_xh[MROWS*DIM], g_xl[MROWS*DIM];
__device__ __align__(16) __nv_bfloat16 g_wqh[QKV_N*DIM], g_wql[QKV_N*DIM]; // W^T [n][k]
__device__ __align__(16) __nv_bfloat16 g_woh[DIM*DIM],   g_wol[DIM*DIM];   // W^T [n][k]
__device__ __align__(16) __nv_bfloat16 g_Qh[BH*SEQ*HD], g_Ql[BH*SEQ*HD];
__device__ __align__(16) __nv_bfloat16 g_Kh[BH*SEQ*HD], g_Kl[BH*SEQ*HD];
__device__ __align__(16) float         g_V[BH*SEQ*HD];
__device__ __align__(16) __nv_bfloat16 g_Vth[BH*HD*SEQ], g_Vtl[BH*HD*SEQ]; // [bh][hd][n]
__device__ __align__(16) __nv_bfloat16 g_Ah[MROWS*DIM], g_Al[MROWS*DIM];   // attn out [B,N,D]

// ---------------- helpers ----------------
__device__ __forceinline__ void mma16816(float* c,
    unsigned a0, unsigned a1, unsigned a2, unsigned a3,
    unsigned b0, unsigned b1)
{
    asm volatile(
        "mma.sync.aligned.m16n8k16.row.col.f32.bf16.bf16.f32 "
        "{%0,%1,%2,%3}, {%4,%5,%6,%7}, {%8,%9}, {%0,%1,%2,%3};"
        : "+f"(c[0]), "+f"(c[1]), "+f"(c[2]), "+f"(c[3])
        : "r"(a0), "r"(a1), "r"(a2), "r"(a3), "r"(b0), "r"(b1));
}

__device__ __forceinline__ void bsplit2(float x, float y,
                                        unsigned& hi, unsigned& lo)
{
    __nv_bfloat162 h2, l2;
    h2.x = __float2bfloat16(x);
    h2.y = __float2bfloat16(y);
    l2.x = __float2bfloat16(x - __bfloat162float(h2.x));
    l2.y = __float2bfloat16(y - __bfloat162float(h2.y));
    hi = *reinterpret_cast<unsigned*>(&h2);
    lo = *reinterpret_cast<unsigned*>(&l2);
}

__device__ __forceinline__ void bsplit2v(float x, float y,
                                         __nv_bfloat162& h2, __nv_bfloat162& l2)
{
    h2.x = __float2bfloat16(x);
    h2.y = __float2bfloat16(y);
    l2.x = __float2bfloat16(x - __bfloat162float(h2.x));
    l2.y = __float2bfloat16(y - __bfloat162float(h2.y));
}

__device__ __forceinline__ void cpa16(void* s, const void* g)
{
    unsigned sa = (unsigned)__cvta_generic_to_shared(s);
    asm volatile("cp.async.cg.shared.global [%0], [%1], 16;" :: "r"(sa), "l"(g));
}
#define CP_COMMIT() asm volatile("cp.async.commit_group;" ::: "memory")
#define CP_WAIT1()  asm volatile("cp.async.wait_group 1;" ::: "memory")
#define CP_WAIT0()  asm volatile("cp.async.wait_group 0;" ::: "memory")

// ---------------- pre-pass converts ----------------
__global__ __launch_bounds__(256) void split_x(const float* __restrict__ x)
{
    int i = blockIdx.x * 256 + threadIdx.x;        // float4 index
    float4 v = ((const float4*)x)[i];
    unsigned h0, l0, h1, l1;
    bsplit2(v.x, v.y, h0, l0);
    bsplit2(v.z, v.w, h1, l1);
    ((uint2*)g_xh)[i] = make_uint2(h0, h1);
    ((uint2*)g_xl)[i] = make_uint2(l0, l1);
}

__global__ __launch_bounds__(256) void tsplit_w(const float* __restrict__ W,
                                                int N, int which)
{
    __shared__ float t[32][33];
    __nv_bfloat16* Th = which ? g_woh : g_wqh;
    __nv_bfloat16* Tl = which ? g_wol : g_wql;
    const int n0 = blockIdx.x * 32, k0 = blockIdx.y * 32;
    const int tx = threadIdx.x & 31, ty = threadIdx.x >> 5;
    for (int r = ty; r < 32; r += 8)
        t[r][tx] = W[(size_t)(k0 + r) * N + n0 + tx];
    __syncthreads();
    for (int r = ty; r < 32; r += 8) {
        float v = t[tx][r];
        __nv_bfloat16 h = __float2bfloat16(v);
        size_t o = (size_t)(n0 + r) * DIM + k0 + tx;
        Th[o] = h;
        Tl[o] = __float2bfloat16(v - __bfloat162float(h));
    }
}

// ---------------- pipelined 3-term split-bf16 GEMM core --------------------
// CTA tile 128x128, 128 threads = 4 warps in 2x2 grid, warp tile 64x64.
// Dynamic smem: 2 stages x 4 arrays (Ah,Al,Bh,Bl) x 128x40 bf16 = 81920 B.
#define GPAD 40
#define GST  (128*GPAD)
extern __shared__ __nv_bfloat16 dynsmem[];

#define GEMM_LOAD_STAGE(k0, st)                                               \
    do {                                                                      \
        _Pragma("unroll")                                                     \
        for (int c = 0; c < 4; c++) {                                         \
            int i = tid + c * 128;                                            \
            int r = i >> 2, sg = (i & 3) * 8;                                 \
            size_t ga = (size_t)(row0 + r) * K + (k0) + sg;                   \
            size_t gb = (size_t)(col0 + r) * K + (k0) + sg;                   \
            cpa16(dynsmem + ((st) * 4 + 0) * GST + r * GPAD + sg, Ahg + ga);  \
            cpa16(dynsmem + ((st) * 4 + 1) * GST + r * GPAD + sg, Alg + ga);  \
            cpa16(dynsmem + ((st) * 4 + 2) * GST + r * GPAD + sg, Bhg + gb);  \
            cpa16(dynsmem + ((st) * 4 + 3) * GST + r * GPAD + sg, Blg + gb);  \
        }                                                                     \
        CP_COMMIT();                                                          \
    } while (0)

__device__ __forceinline__ void gemm_core(
    const __nv_bfloat16* __restrict__ Ahg, const __nv_bfloat16* __restrict__ Alg,
    const __nv_bfloat16* __restrict__ Bhg, const __nv_bfloat16* __restrict__ Blg,
    int K, int row0, int col0, float acc[4][8][4])
{
    const int tid = threadIdx.x;
    const int warp = tid >> 5, lane = tid & 31;
    const int g = lane >> 2, tig = lane & 3;
    const int wm = (warp & 1) * 64, wn = (warp >> 1) * 64;

    GEMM_LOAD_STAGE(0, 0);
    int p = 0;
    for (int k0 = 0; k0 < K; k0 += 32) {
        if (k0 + 32 < K) {
            GEMM_LOAD_STAGE(k0 + 32, p ^ 1);
            CP_WAIT1();
        } else {
            CP_WAIT0();
        }
        __syncthreads();

        const __nv_bfloat16* ASH = dynsmem + (p * 4 + 0) * GST;
        const __nv_bfloat16* ASL = dynsmem + (p * 4 + 1) * GST;
        const __nv_bfloat16* BSH = dynsmem + (p * 4 + 2) * GST;
        const __nv_bfloat16* BSL = dynsmem + (p * 4 + 3) * GST;

#pragma unroll
        for (int kc = 0; kc < 2; kc++) {
            const int c0 = kc * 16 + 2 * tig;
            unsigned afh[4][4], afl[4][4];
#pragma unroll
            for (int mt = 0; mt < 4; mt++) {
                int m0 = wm + mt * 16;
                afh[mt][0] = *(const unsigned*)&ASH[(m0 + g) * GPAD + c0];
                afh[mt][1] = *(const unsigned*)&ASH[(m0 + g + 8) * GPAD + c0];
                afh[mt][2] = *(const unsigned*)&ASH[(m0 + g) * GPAD + c0 + 8];
                afh[mt][3] = *(const unsigned*)&ASH[(m0 + g + 8) * GPAD + c0 + 8];
                afl[mt][0] = *(const unsigned*)&ASL[(m0 + g) * GPAD + c0];
                afl[mt][1] = *(const unsigned*)&ASL[(m0 + g + 8) * GPAD + c0];
                afl[mt][2] = *(const unsigned*)&ASL[(m0 + g) * GPAD + c0 + 8];
                afl[mt][3] = *(const unsigned*)&ASL[(m0 + g + 8) * GPAD + c0 + 8];
            }
#pragma unroll
            for (int nt = 0; nt < 8; nt++) {
                int nr = wn + nt * 8 + g;
                unsigned bh0 = *(const unsigned*)&BSH[nr * GPAD + c0];
                unsigned bh1 = *(const unsigned*)&BSH[nr * GPAD + c0 + 8];
                unsigned bl0 = *(const unsigned*)&BSL[nr * GPAD + c0];
                unsigned bl1 = *(const unsigned*)&BSL[nr * GPAD + c0 + 8];
#pragma unroll
                for (int mt = 0; mt < 4; mt++) {
                    mma16816(acc[mt][nt], afh[mt][0], afh[mt][1], afh[mt][2], afh[mt][3], bh0, bh1);
                    mma16816(acc[mt][nt], afh[mt][0], afh[mt][1], afh[mt][2], afh[mt][3], bl0, bl1);
                    mma16816(acc[mt][nt], afl[mt][0], afl[mt][1], afl[mt][2], afl[mt][3], bh0, bh1);
                }
            }
        }
        __syncthreads();
        p ^= 1;
    }
}

// ---------------- GEMM 1: qkv, epilogue scatters split Q/K + fp32 V --------
__global__ __launch_bounds__(128) void gemm_qkv_mma(const float* __restrict__ bias)
{
    float acc[4][8][4];
#pragma unroll
    for (int mt = 0; mt < 4; mt++)
#pragma unroll
        for (int nt = 0; nt < 8; nt++)
#pragma unroll
            for (int e = 0; e < 4; e++) acc[mt][nt][e] = 0.f;

    const int row0 = blockIdx.y * 128, col0 = blockIdx.x * 128;
    gemm_core(g_xh, g_xl, g_wqh, g_wql, DIM, row0, col0, acc);

    const int lane = threadIdx.x & 31, warp = threadIdx.x >> 5;
    const int g = lane >> 2, tig = lane & 3;
    const int wm = (warp & 1) * 64, wn = (warp >> 1) * 64;

#pragma unroll
    for (int nt = 0; nt < 8; nt++) {
        int cb = col0 + wn + nt * 8 + 2 * tig;
        float bv0 = bias[cb], bv1 = bias[cb + 1];
        int s = cb >> 10, rr = cb & (DIM - 1);
        int h = rr >> 6, d = rr & (HD - 1);
#pragma unroll
        for (int mt = 0; mt < 4; mt++) {
#pragma unroll
            for (int half = 0; half < 2; half++) {
                int r = row0 + wm + mt * 16 + g + 8 * half;
                float v0 = acc[mt][nt][2 * half + 0] + bv0;
                float v1 = acc[mt][nt][2 * half + 1] + bv1;
                int b_ = r >> 11, n = r & (SEQ - 1);
                size_t idx = (((size_t)(b_ * HEADS + h) * SEQ) + n) * HD + d;
                if (s == 0) {
                    __nv_bfloat162 hh, ll;
                    bsplit2v(v0 * 0.125f, v1 * 0.125f, hh, ll);
                    *(__nv_bfloat162*)&g_Qh[idx] = hh;
                    *(__nv_bfloat162*)&g_Ql[idx] = ll;
                } else if (s == 1) {
                    __nv_bfloat162 hh, ll;
                    bsplit2v(v0, v1, hh, ll);
                    *(__nv_bfloat162*)&g_Kh[idx] = hh;
                    *(__nv_bfloat162*)&g_Kl[idx] = ll;
                } else {
                    *(float2*)&g_V[idx] = make_float2(v0, v1);
                }
            }
        }
    }
}

// ---------------- V transpose + split ----------------
__global__ __launch_bounds__(256) void convert_v()
{
    __shared__ float vt[64][65];
    const int bh = blockIdx.y;
    const int s0 = blockIdx.x * 64;
    const int tid = threadIdx.x;
    const size_t base = ((size_t)bh * SEQ + s0) * HD;

    for (int i = tid; i < 64 * HD; i += 256) {
        int s = i >> 6, d = i & 63;
        vt[s][d] = g_V[base + i];
    }
    __syncthreads();
    for (int i = tid; i < 64 * HD; i += 256) {
        int d = i >> 6, s = i & 63;
        float v = vt[s][d];
        __nv_bfloat16 vh = __float2bfloat16(v);
        size_t o = ((size_t)bh * HD + d) * SEQ + s0 + s;
        g_Vth[o] = vh;
        g_Vtl[o] = __float2bfloat16(v - __bfloat162float(vh));
    }
}

// ---------------- tensor-core flash attention (unchanged from R7) ----------
#define KSP 72
#define VSP 40

#define ATTN_LOAD_STAGE(kt, st)                                               \
    do {                                                                      \
        _Pragma("unroll")                                                     \
        for (int c = 0; c < 2; c++) {                                         \
            int i = tid + c * 128;                                            \
            int r = i >> 3, seg = i & 7;                                      \
            size_t ko = (size_t)((kt) + r) * HD + seg * 8;                    \
            cpa16(&Ksh[st][r][seg * 8], Khg + ko);                            \
            cpa16(&Ksl[st][r][seg * 8], Klg + ko);                            \
            int rv = i >> 2, sv = i & 3;                                      \
            size_t vo = (size_t)rv * SEQ + (kt) + sv * 8;                     \
            cpa16(&Vsh[st][rv][sv * 8], Vthg + vo);                           \
            cpa16(&Vsl[st][rv][sv * 8], Vtlg + vo);                           \
        }                                                                     \
        CP_COMMIT();                                                          \
    } while (0)

__global__ __launch_bounds__(128) void attn_mma()
{
    __shared__ __nv_bfloat16 Ksh[2][32][KSP];
    __shared__ __nv_bfloat16 Ksl[2][32][KSP];
    __shared__ __nv_bfloat16 Vsh[2][HD][VSP];
    __shared__ __nv_bfloat16 Vsl[2][HD][VSP];

    const int tid  = threadIdx.x;
    const int warp = tid >> 5;
    const int lane = tid & 31;
    const int g    = lane >> 2;
    const int tig  = lane & 3;

    const int bh = blockIdx.y;
    const int q0 = blockIdx.x * 64;
    const int qbase = q0 + warp * 16;

    const __nv_bfloat16* Khg = g_Kh + (size_t)bh * SEQ * HD;
    const __nv_bfloat16* Klg = g_Kl + (size_t)bh * SEQ * HD;
    const __nv_bfloat16* Vthg = g_Vth + (size_t)bh * HD * SEQ;
    const __nv_bfloat16* Vtlg = g_Vtl + (size_t)bh * HD * SEQ;

    ATTN_LOAD_STAGE(0, 0);

    unsigned aqh[4][4], aql[4][4];
    {
        const __nv_bfloat16* Qh = g_Qh + ((size_t)bh * SEQ + qbase) * HD;
        const __nv_bfloat16* Ql = g_Ql + ((size_t)bh * SEQ + qbase) * HD;
#pragma unroll
        for (int kc = 0; kc < 4; kc++) {
            int d0 = 16 * kc + 2 * tig;
            aqh[kc][0] = *(const unsigned*)&Qh[(size_t)g * HD + d0];
            aqh[kc][1] = *(const unsigned*)&Qh[(size_t)(g + 8) * HD + d0];
            aqh[kc][2] = *(const unsigned*)&Qh[(size_t)g * HD + d0 + 8];
            aqh[kc][3] = *(const unsigned*)&Qh[(size_t)(g + 8) * HD + d0 + 8];
            aql[kc][0] = *(const unsigned*)&Ql[(size_t)g * HD + d0];
            aql[kc][1] = *(const unsigned*)&Ql[(size_t)(g + 8) * HD + d0];
            aql[kc][2] = *(const unsigned*)&Ql[(size_t)g * HD + d0 + 8];
            aql[kc][3] = *(const unsigned*)&Ql[(size_t)(g + 8) * HD + d0 + 8];
        }
    }

    float oacc[8][4];
#pragma unroll
    for (int dt = 0; dt < 8; dt++)
#pragma unroll
        for (int e = 0; e < 4; e++) oacc[dt][e] = 0.f;
    float m0 = -1e30f, m1 = -1e30f, l0 = 0.f, l1 = 0.f;

    int p = 0;
    for (int kt = 0; kt < SEQ; kt += 32) {
        if (kt + 32 < SEQ) {
            ATTN_LOAD_STAGE(kt + 32, p ^ 1);
            CP_WAIT1();
        } else {
            CP_WAIT0();
        }
        __syncthreads();

        float sacc[4][4];
#pragma unroll
        for (int j = 0; j < 4; j++) {
#pragma unroll
            for (int e = 0; e < 4; e++) sacc[j][e] = 0.f;
            int key = 8 * j + g;
#pragma unroll
            for (int kc = 0; kc < 4; kc++) {
                int d0 = 16 * kc + 2 * tig;
                unsigned bh0 = *(const unsigned*)&Ksh[p][key][d0];
                unsigned bh1 = *(const unsigned*)&Ksh[p][key][d0 + 8];
                unsigned bl0 = *(const unsigned*)&Ksl[p][key][d0];
                unsigned bl1 = *(const unsigned*)&Ksl[p][key][d0 + 8];
                mma16816(sacc[j], aqh[kc][0], aqh[kc][1], aqh[kc][2], aqh[kc][3], bh0, bh1);
                mma16816(sacc[j], aqh[kc][0], aqh[kc][1], aqh[kc][2], aqh[kc][3], bl0, bl1);
                mma16816(sacc[j], aql[kc][0], aql[kc][1], aql[kc][2], aql[kc][3], bh0, bh1);
            }
        }

        float r0 = -1e30f, r1 = -1e30f;
#pragma unroll
        for (int j = 0; j < 4; j++) {
            r0 = fmaxf(r0, fmaxf(sacc[j][0], sacc[j][1]));
            r1 = fmaxf(r1, fmaxf(sacc[j][2], sacc[j][3]));
        }
        r0 = fmaxf(r0, __shfl_xor_sync(0xFFFFFFFFu, r0, 1));
        r0 = fmaxf(r0, __shfl_xor_sync(0xFFFFFFFFu, r0, 2));
        r1 = fmaxf(r1, __shfl_xor_sync(0xFFFFFFFFu, r1, 1));
        r1 = fmaxf(r1, __shfl_xor_sync(0xFFFFFFFFu, r1, 2));
        float mn0 = fmaxf(m0, r0), mn1 = fmaxf(m1, r1);
        float corr0 = __expf(m0 - mn0), corr1 = __expf(m1 - mn1);
        m0 = mn0; m1 = mn1;

        float ls0 = 0.f, ls1 = 0.f;
#pragma unroll
        for (int j = 0; j < 4; j++) {
            sacc[j][0] = __expf(sacc[j][0] - mn0);
            sacc[j][1] = __expf(sacc[j][1] - mn0);
            sacc[j][2] = __expf(sacc[j][2] - mn1);
            sacc[j][3] = __expf(sacc[j][3] - mn1);
            ls0 += sacc[j][0] + sacc[j][1];
            ls1 += sacc[j][2] + sacc[j][3];
        }
        ls0 += __shfl_xor_sync(0xFFFFFFFFu, ls0, 1);
        ls0 += __shfl_xor_sync(0xFFFFFFFFu, ls0, 2);
        ls1 += __shfl_xor_sync(0xFFFFFFFFu, ls1, 1);
        ls1 += __shfl_xor_sync(0xFFFFFFFFu, ls1, 2);
        l0 = l0 * corr0 + ls0;
        l1 = l1 * corr1 + ls1;

#pragma unroll
        for (int dt = 0; dt < 8; dt++) {
            oacc[dt][0] *= corr0; oacc[dt][1] *= corr0;
            oacc[dt][2] *= corr1; oacc[dt][3] *= corr1;
        }

        unsigned aph[2][4], apl[2][4];
#pragma unroll
        for (int kc2 = 0; kc2 < 2; kc2++) {
            int j0 = 2 * kc2, j1 = 2 * kc2 + 1;
            bsplit2(sacc[j0][0], sacc[j0][1], aph[kc2][0], apl[kc2][0]);
            bsplit2(sacc[j0][2], sacc[j0][3], aph[kc2][1], apl[kc2][1]);
            bsplit2(sacc[j1][0], sacc[j1][1], aph[kc2][2], apl[kc2][2]);
            bsplit2(sacc[j1][2], sacc[j1][3], aph[kc2][3], apl[kc2][3]);
        }

#pragma unroll
        for (int dt = 0; dt < 8; dt++) {
            int drow = 8 * dt + g;
#pragma unroll
            for (int kc2 = 0; kc2 < 2; kc2++) {
                int k0c = 16 * kc2 + 2 * tig;
                unsigned bh0 = *(const unsigned*)&Vsh[p][drow][k0c];
                unsigned bh1 = *(const unsigned*)&Vsh[p][drow][k0c + 8];
                unsigned bl0 = *(const unsigned*)&Vsl[p][drow][k0c];
                unsigned bl1 = *(const unsigned*)&Vsl[p][drow][k0c + 8];
                mma16816(oacc[dt], aph[kc2][0], aph[kc2][1], aph[kc2][2], aph[kc2][3], bh0, bh1);
                mma16816(oacc[dt], aph[kc2][0], aph[kc2][1], aph[kc2][2], aph[kc2][3], bl0, bl1);
                mma16816(oacc[dt], apl[kc2][0], apl[kc2][1], apl[kc2][2], apl[kc2][3], bh0, bh1);
            }
        }
        __syncthreads();
        p ^= 1;
    }

    const int b_ = bh >> 4, h = bh & 15;
    const float inv0 = 1.f / l0, inv1 = 1.f / l1;
    const int qg0 = qbase + g, qg1 = qbase + g + 8;
    const size_t o0 = ((size_t)(b_ * SEQ + qg0)) * DIM + h * HD;
    const size_t o1 = ((size_t)(b_ * SEQ + qg1)) * DIM + h * HD;
#pragma unroll
    for (int dt = 0; dt < 8; dt++) {
        int d = 8 * dt + 2 * tig;
        __nv_bfloat162 hh, ll;
        bsplit2v(oacc[dt][0] * inv0, oacc[dt][1] * inv0, hh, ll);
        *(__nv_bfloat162*)&g_Ah[o0 + d] = hh;
        *(__nv_bfloat162*)&g_Al[o0 + d] = ll;
        bsplit2v(oacc[dt][2] * inv1, oacc[dt][3] * inv1, hh, ll);
        *(__nv_bfloat162*)&g_Ah[o1 + d] = hh;
        *(__nv_bfloat162*)&g_Al[o1 + d] = ll;
    }
}

// ---------------- GEMM 2: out = attn @ w_out + b_out ----------------------
__global__ __launch_bounds__(128) void gemm_out_mma(const float* __restrict__ bias,
                                                    float* __restrict__ out)
{
    float acc[4][8][4];
#pragma unroll
    for (int mt = 0; mt < 4; mt++)
#pragma unroll
        for (int nt = 0; nt < 8; nt++)
#pragma unroll
            for (int e = 0; e < 4; e++) acc[mt][nt][e] = 0.f;

    const int row0 = blockIdx.y * 128, col0 = blockIdx.x * 128;
    gemm_core(g_Ah, g_Al, g_woh, g_wol, DIM, row0, col0, acc);

    const int lane = threadIdx.x & 31, warp = threadIdx.x >> 5;
    const int g = lane >> 2, tig = lane & 3;
    const int wm = (warp & 1) * 64, wn = (warp >> 1) * 64;

#pragma unroll
    for (int nt = 0; nt < 8; nt++) {
        int cb = col0 + wn + nt * 8 + 2 * tig;
        float bv0 = bias[cb], bv1 = bias[cb + 1];
#pragma unroll
        for (int mt = 0; mt < 4; mt++) {
            int r = row0 + wm + mt * 16 + g;
            *(float2*)&out[(size_t)r * DIM + cb] =
                make_float2(acc[mt][nt][0] + bv0, acc[mt][nt][1] + bv1);
            *(float2*)&out[(size_t)(r + 8) * DIM + cb] =
                make_float2(acc[mt][nt][2] + bv0, acc[mt][nt][3] + bv1);
        }
    }
}

extern "C" void kernel_launch(void* const* d_in, const int* in_sizes, int n_in,
                              void* d_out, int out_size)
{
    (void)in_sizes; (void)n_in; (void)out_size;
    const float* x     = (const float*)d_in[0];
    const float* w_qkv = (const float*)d_in[1];
    const float* b_qkv = (const float*)d_in[2];
    const float* w_out = (const float*)d_in[3];
    const float* b_out = (const float*)d_in[4];
    float* out = (float*)d_out;

    const int GEMM_SMEM = 2 * 4 * GST * (int)sizeof(__nv_bfloat16);  // 81920
    cudaFuncSetAttribute(gemm_qkv_mma,
                         cudaFuncAttributeMaxDynamicSharedMemorySize, GEMM_SMEM);
    cudaFuncSetAttribute(gemm_out_mma,
                         cudaFuncAttributeMaxDynamicSharedMemorySize, GEMM_SMEM);

    split_x<<<MROWS * DIM / 1024, 256>>>(x);
    tsplit_w<<<dim3(QKV_N / 32, DIM / 32), 256>>>(w_qkv, QKV_N, 0);
    tsplit_w<<<dim3(DIM / 32, DIM / 32), 256>>>(w_out, DIM, 1);
    gemm_qkv_mma<<<dim3(QKV_N / 128, MROWS / 128), 128, GEMM_SMEM>>>(b_qkv);
    convert_v<<<dim3(SEQ / 64, BH), 256>>>();
    attn_mma<<<dim3(SEQ / 64, BH), 128>>>();
    gemm_out_mma<<<dim3(DIM / 128, MROWS / 128), 128, GEMM_SMEM>>>(b_out, out);
}

// round 10
// speedup vs baseline: 5.7423x; 1.0366x over previous
#include <cuda_runtime.h>
#include <cuda_bf16.h>

#define BATCH 2
#define HEADS 16
#define SEQ   2048
#define DIM   1024
#define HD    64
#define QKV_N (3*DIM)
#define MROWS (BATCH*SEQ)   // 4096
#define BH    (BATCH*HEADS) // 32

// ---------------- scratch (no allocations allowed) ----------------
__device__ __align__(16) __nv_bfloat16 g_xh[MROWS*DIM], g_xl[MROWS*DIM];
__device__ __align__(16) __nv_bfloat16 g_wqh[QKV_N*DIM], g_wql[QKV_N*DIM]; // W^T [n][k]
__device__ __align__(16) __nv_bfloat16 g_woh[DIM*DIM],   g_wol[DIM*DIM];   // W^T [n][k]
__device__ __align__(16) __nv_bfloat16 g_Qh[BH*SEQ*HD], g_Ql[BH*SEQ*HD];
__device__ __align__(16) __nv_bfloat16 g_Kh[BH*SEQ*HD], g_Kl[BH*SEQ*HD];
__device__ __align__(16) float         g_V[BH*SEQ*HD];
__device__ __align__(16) __nv_bfloat16 g_Vth[BH*HD*SEQ], g_Vtl[BH*HD*SEQ]; // [bh][hd][n]
__device__ __align__(16) __nv_bfloat16 g_Ah[MROWS*DIM], g_Al[MROWS*DIM];   // attn out [B,N,D]

// ---------------- helpers ----------------
__device__ __forceinline__ void mma16816(float* c,
    unsigned a0, unsigned a1, unsigned a2, unsigned a3,
    unsigned b0, unsigned b1)
{
    asm volatile(
        "mma.sync.aligned.m16n8k16.row.col.f32.bf16.bf16.f32 "
        "{%0,%1,%2,%3}, {%4,%5,%6,%7}, {%8,%9}, {%0,%1,%2,%3};"
        : "+f"(c[0]), "+f"(c[1]), "+f"(c[2]), "+f"(c[3])
        : "r"(a0), "r"(a1), "r"(a2), "r"(a3), "r"(b0), "r"(b1));
}

__device__ __forceinline__ void bsplit2(float x, float y,
                                        unsigned& hi, unsigned& lo)
{
    __nv_bfloat162 h2, l2;
    h2.x = __float2bfloat16(x);
    h2.y = __float2bfloat16(y);
    l2.x = __float2bfloat16(x - __bfloat162float(h2.x));
    l2.y = __float2bfloat16(y - __bfloat162float(h2.y));
    hi = *reinterpret_cast<unsigned*>(&h2);
    lo = *reinterpret_cast<unsigned*>(&l2);
}

__device__ __forceinline__ void bsplit2v(float x, float y,
                                         __nv_bfloat162& h2, __nv_bfloat162& l2)
{
    h2.x = __float2bfloat16(x);
    h2.y = __float2bfloat16(y);
    l2.x = __float2bfloat16(x - __bfloat162float(h2.x));
    l2.y = __float2bfloat16(y - __bfloat162float(h2.y));
}

__device__ __forceinline__ void cpa16(void* s, const void* g)
{
    unsigned sa = (unsigned)__cvta_generic_to_shared(s);
    asm volatile("cp.async.cg.shared.global [%0], [%1], 16;" :: "r"(sa), "l"(g));
}
#define CP_COMMIT() asm volatile("cp.async.commit_group;" ::: "memory")
#define CP_WAIT1()  asm volatile("cp.async.wait_group 1;" ::: "memory")
#define CP_WAIT0()  asm volatile("cp.async.wait_group 0;" ::: "memory")

// ---------------- pre-pass converts ----------------
__global__ __launch_bounds__(256) void split_x(const float* __restrict__ x)
{
    int i = blockIdx.x * 256 + threadIdx.x;        // float4 index
    float4 v = ((const float4*)x)[i];
    unsigned h0, l0, h1, l1;
    bsplit2(v.x, v.y, h0, l0);
    bsplit2(v.z, v.w, h1, l1);
    ((uint2*)g_xh)[i] = make_uint2(h0, h1);
    ((uint2*)g_xl)[i] = make_uint2(l0, l1);
}

__global__ __launch_bounds__(256) void tsplit_w(const float* __restrict__ W,
                                                int N, int which)
{
    __shared__ float t[32][33];
    __nv_bfloat16* Th = which ? g_woh : g_wqh;
    __nv_bfloat16* Tl = which ? g_wol : g_wql;
    const int n0 = blockIdx.x * 32, k0 = blockIdx.y * 32;
    const int tx = threadIdx.x & 31, ty = threadIdx.x >> 5;
    for (int r = ty; r < 32; r += 8)
        t[r][tx] = W[(size_t)(k0 + r) * N + n0 + tx];
    __syncthreads();
    for (int r = ty; r < 32; r += 8) {
        float v = t[tx][r];
        __nv_bfloat16 h = __float2bfloat16(v);
        size_t o = (size_t)(n0 + r) * DIM + k0 + tx;
        Th[o] = h;
        Tl[o] = __float2bfloat16(v - __bfloat162float(h));
    }
}

// ---------------- pipelined 3-term split-bf16 GEMM core --------------------
// CTA tile 128x128, 128 threads = 4 warps in 2x2 grid, warp tile 64x64.
// MMA issue order: term-outer over mt (same-acc reuse distance 4).
#define GPAD 40
#define GST  (128*GPAD)
extern __shared__ __nv_bfloat16 dynsmem[];

#define GEMM_LOAD_STAGE(k0, st)                                               \
    do {                                                                      \
        _Pragma("unroll")                                                     \
        for (int c = 0; c < 4; c++) {                                         \
            int i = tid + c * 128;                                            \
            int r = i >> 2, sg = (i & 3) * 8;                                 \
            size_t ga = (size_t)(row0 + r) * K + (k0) + sg;                   \
            size_t gb = (size_t)(col0 + r) * K + (k0) + sg;                   \
            cpa16(dynsmem + ((st) * 4 + 0) * GST + r * GPAD + sg, Ahg + ga);  \
            cpa16(dynsmem + ((st) * 4 + 1) * GST + r * GPAD + sg, Alg + ga);  \
            cpa16(dynsmem + ((st) * 4 + 2) * GST + r * GPAD + sg, Bhg + gb);  \
            cpa16(dynsmem + ((st) * 4 + 3) * GST + r * GPAD + sg, Blg + gb);  \
        }                                                                     \
        CP_COMMIT();                                                          \
    } while (0)

__device__ __forceinline__ void gemm_core(
    const __nv_bfloat16* __restrict__ Ahg, const __nv_bfloat16* __restrict__ Alg,
    const __nv_bfloat16* __restrict__ Bhg, const __nv_bfloat16* __restrict__ Blg,
    int K, int row0, int col0, float acc[4][8][4])
{
    const int tid = threadIdx.x;
    const int warp = tid >> 5, lane = tid & 31;
    const int g = lane >> 2, tig = lane & 3;
    const int wm = (warp & 1) * 64, wn = (warp >> 1) * 64;

    GEMM_LOAD_STAGE(0, 0);
    int p = 0;
    for (int k0 = 0; k0 < K; k0 += 32) {
        if (k0 + 32 < K) {
            GEMM_LOAD_STAGE(k0 + 32, p ^ 1);
            CP_WAIT1();
        } else {
            CP_WAIT0();
        }
        __syncthreads();

        const __nv_bfloat16* ASH = dynsmem + (p * 4 + 0) * GST;
        const __nv_bfloat16* ASL = dynsmem + (p * 4 + 1) * GST;
        const __nv_bfloat16* BSH = dynsmem + (p * 4 + 2) * GST;
        const __nv_bfloat16* BSL = dynsmem + (p * 4 + 3) * GST;

#pragma unroll
        for (int kc = 0; kc < 2; kc++) {
            const int c0 = kc * 16 + 2 * tig;
            unsigned afh[4][4], afl[4][4];
#pragma unroll
            for (int mt = 0; mt < 4; mt++) {
                int m0 = wm + mt * 16;
                afh[mt][0] = *(const unsigned*)&ASH[(m0 + g) * GPAD + c0];
                afh[mt][1] = *(const unsigned*)&ASH[(m0 + g + 8) * GPAD + c0];
                afh[mt][2] = *(const unsigned*)&ASH[(m0 + g) * GPAD + c0 + 8];
                afh[mt][3] = *(const unsigned*)&ASH[(m0 + g + 8) * GPAD + c0 + 8];
                afl[mt][0] = *(const unsigned*)&ASL[(m0 + g) * GPAD + c0];
                afl[mt][1] = *(const unsigned*)&ASL[(m0 + g + 8) * GPAD + c0];
                afl[mt][2] = *(const unsigned*)&ASL[(m0 + g) * GPAD + c0 + 8];
                afl[mt][3] = *(const unsigned*)&ASL[(m0 + g + 8) * GPAD + c0 + 8];
            }
#pragma unroll
            for (int nt = 0; nt < 8; nt++) {
                int nr = wn + nt * 8 + g;
                unsigned bh0 = *(const unsigned*)&BSH[nr * GPAD + c0];
                unsigned bh1 = *(const unsigned*)&BSH[nr * GPAD + c0 + 8];
                unsigned bl0 = *(const unsigned*)&BSL[nr * GPAD + c0];
                unsigned bl1 = *(const unsigned*)&BSL[nr * GPAD + c0 + 8];
                // term hh across all mt (distance-4 acc reuse)
#pragma unroll
                for (int mt = 0; mt < 4; mt++)
                    mma16816(acc[mt][nt], afh[mt][0], afh[mt][1], afh[mt][2], afh[mt][3], bh0, bh1);
                // term hl
#pragma unroll
                for (int mt = 0; mt < 4; mt++)
                    mma16816(acc[mt][nt], afh[mt][0], afh[mt][1], afh[mt][2], afh[mt][3], bl0, bl1);
                // term lh
#pragma unroll
                for (int mt = 0; mt < 4; mt++)
                    mma16816(acc[mt][nt], afl[mt][0], afl[mt][1], afl[mt][2], afl[mt][3], bh0, bh1);
            }
        }
        __syncthreads();
        p ^= 1;
    }
}

// ---------------- GEMM 1: qkv, epilogue scatters split Q/K + fp32 V --------
__global__ __launch_bounds__(128) void gemm_qkv_mma(const float* __restrict__ bias)
{
    float acc[4][8][4];
#pragma unroll
    for (int mt = 0; mt < 4; mt++)
#pragma unroll
        for (int nt = 0; nt < 8; nt++)
#pragma unroll
            for (int e = 0; e < 4; e++) acc[mt][nt][e] = 0.f;

    const int row0 = blockIdx.y * 128, col0 = blockIdx.x * 128;
    gemm_core(g_xh, g_xl, g_wqh, g_wql, DIM, row0, col0, acc);

    const int lane = threadIdx.x & 31, warp = threadIdx.x >> 5;
    const int g = lane >> 2, tig = lane & 3;
    const int wm = (warp & 1) * 64, wn = (warp >> 1) * 64;

#pragma unroll
    for (int nt = 0; nt < 8; nt++) {
        int cb = col0 + wn + nt * 8 + 2 * tig;
        float bv0 = bias[cb], bv1 = bias[cb + 1];
        int s = cb >> 10, rr = cb & (DIM - 1);
        int h = rr >> 6, d = rr & (HD - 1);
#pragma unroll
        for (int mt = 0; mt < 4; mt++) {
#pragma unroll
            for (int half = 0; half < 2; half++) {
                int r = row0 + wm + mt * 16 + g + 8 * half;
                float v0 = acc[mt][nt][2 * half + 0] + bv0;
                float v1 = acc[mt][nt][2 * half + 1] + bv1;
                int b_ = r >> 11, n = r & (SEQ - 1);
                size_t idx = (((size_t)(b_ * HEADS + h) * SEQ) + n) * HD + d;
                if (s == 0) {
                    __nv_bfloat162 hh, ll;
                    bsplit2v(v0 * 0.125f, v1 * 0.125f, hh, ll);
                    *(__nv_bfloat162*)&g_Qh[idx] = hh;
                    *(__nv_bfloat162*)&g_Ql[idx] = ll;
                } else if (s == 1) {
                    __nv_bfloat162 hh, ll;
                    bsplit2v(v0, v1, hh, ll);
                    *(__nv_bfloat162*)&g_Kh[idx] = hh;
                    *(__nv_bfloat162*)&g_Kl[idx] = ll;
                } else {
                    *(float2*)&g_V[idx] = make_float2(v0, v1);
                }
            }
        }
    }
}

// ---------------- V transpose + split ----------------
__global__ __launch_bounds__(256) void convert_v()
{
    __shared__ float vt[64][65];
    const int bh = blockIdx.y;
    const int s0 = blockIdx.x * 64;
    const int tid = threadIdx.x;
    const size_t base = ((size_t)bh * SEQ + s0) * HD;

    for (int i = tid; i < 64 * HD; i += 256) {
        int s = i >> 6, d = i & 63;
        vt[s][d] = g_V[base + i];
    }
    __syncthreads();
    for (int i = tid; i < 64 * HD; i += 256) {
        int d = i >> 6, s = i & 63;
        float v = vt[s][d];
        __nv_bfloat16 vh = __float2bfloat16(v);
        size_t o = ((size_t)bh * HD + d) * SEQ + s0 + s;
        g_Vth[o] = vh;
        g_Vtl[o] = __float2bfloat16(v - __bfloat162float(vh));
    }
}

// ---------------- tensor-core flash attention (ILP-reordered MMAs) ---------
#define KSP 72
#define VSP 40

#define ATTN_LOAD_STAGE(kt, st)                                               \
    do {                                                                      \
        _Pragma("unroll")                                                     \
        for (int c = 0; c < 2; c++) {                                         \
            int i = tid + c * 128;                                            \
            int r = i >> 3, seg = i & 7;                                      \
            size_t ko = (size_t)((kt) + r) * HD + seg * 8;                    \
            cpa16(&Ksh[st][r][seg * 8], Khg + ko);                            \
            cpa16(&Ksl[st][r][seg * 8], Klg + ko);                            \
            int rv = i >> 2, sv = i & 3;                                      \
            size_t vo = (size_t)rv * SEQ + (kt) + sv * 8;                     \
            cpa16(&Vsh[st][rv][sv * 8], Vthg + vo);                           \
            cpa16(&Vsl[st][rv][sv * 8], Vtlg + vo);                           \
        }                                                                     \
        CP_COMMIT();                                                          \
    } while (0)

__global__ __launch_bounds__(128) void attn_mma()
{
    __shared__ __nv_bfloat16 Ksh[2][32][KSP];
    __shared__ __nv_bfloat16 Ksl[2][32][KSP];
    __shared__ __nv_bfloat16 Vsh[2][HD][VSP];
    __shared__ __nv_bfloat16 Vsl[2][HD][VSP];

    const int tid  = threadIdx.x;
    const int warp = tid >> 5;
    const int lane = tid & 31;
    const int g    = lane >> 2;
    const int tig  = lane & 3;

    const int bh = blockIdx.y;
    const int q0 = blockIdx.x * 64;
    const int qbase = q0 + warp * 16;

    const __nv_bfloat16* Khg = g_Kh + (size_t)bh * SEQ * HD;
    const __nv_bfloat16* Klg = g_Kl + (size_t)bh * SEQ * HD;
    const __nv_bfloat16* Vthg = g_Vth + (size_t)bh * HD * SEQ;
    const __nv_bfloat16* Vtlg = g_Vtl + (size_t)bh * HD * SEQ;

    ATTN_LOAD_STAGE(0, 0);

    unsigned aqh[4][4], aql[4][4];
    {
        const __nv_bfloat16* Qh = g_Qh + ((size_t)bh * SEQ + qbase) * HD;
        const __nv_bfloat16* Ql = g_Ql + ((size_t)bh * SEQ + qbase) * HD;
#pragma unroll
        for (int kc = 0; kc < 4; kc++) {
            int d0 = 16 * kc + 2 * tig;
            aqh[kc][0] = *(const unsigned*)&Qh[(size_t)g * HD + d0];
            aqh[kc][1] = *(const unsigned*)&Qh[(size_t)(g + 8) * HD + d0];
            aqh[kc][2] = *(const unsigned*)&Qh[(size_t)g * HD + d0 + 8];
            aqh[kc][3] = *(const unsigned*)&Qh[(size_t)(g + 8) * HD + d0 + 8];
            aql[kc][0] = *(const unsigned*)&Ql[(size_t)g * HD + d0];
            aql[kc][1] = *(const unsigned*)&Ql[(size_t)(g + 8) * HD + d0];
            aql[kc][2] = *(const unsigned*)&Ql[(size_t)g * HD + d0 + 8];
            aql[kc][3] = *(const unsigned*)&Ql[(size_t)(g + 8) * HD + d0 + 8];
        }
    }

    float oacc[8][4];
#pragma unroll
    for (int dt = 0; dt < 8; dt++)
#pragma unroll
        for (int e = 0; e < 4; e++) oacc[dt][e] = 0.f;
    float m0 = -1e30f, m1 = -1e30f, l0 = 0.f, l1 = 0.f;

    int p = 0;
    for (int kt = 0; kt < SEQ; kt += 32) {
        if (kt + 32 < SEQ) {
            ATTN_LOAD_STAGE(kt + 32, p ^ 1);
            CP_WAIT1();
        } else {
            CP_WAIT0();
        }
        __syncthreads();

        // --- QK^T: kc-outer, K-frag hoist, term-outer over j (dist 4) ---
        float sacc[4][4];
#pragma unroll
        for (int j = 0; j < 4; j++)
#pragma unroll
            for (int e = 0; e < 4; e++) sacc[j][e] = 0.f;

#pragma unroll
        for (int kc = 0; kc < 4; kc++) {
            const int d0 = 16 * kc + 2 * tig;
            unsigned kh0[4], kh1[4], kl0[4], kl1[4];
#pragma unroll
            for (int j = 0; j < 4; j++) {
                int key = 8 * j + g;
                kh0[j] = *(const unsigned*)&Ksh[p][key][d0];
                kh1[j] = *(const unsigned*)&Ksh[p][key][d0 + 8];
                kl0[j] = *(const unsigned*)&Ksl[p][key][d0];
                kl1[j] = *(const unsigned*)&Ksl[p][key][d0 + 8];
            }
#pragma unroll
            for (int j = 0; j < 4; j++)
                mma16816(sacc[j], aqh[kc][0], aqh[kc][1], aqh[kc][2], aqh[kc][3], kh0[j], kh1[j]);
#pragma unroll
            for (int j = 0; j < 4; j++)
                mma16816(sacc[j], aqh[kc][0], aqh[kc][1], aqh[kc][2], aqh[kc][3], kl0[j], kl1[j]);
#pragma unroll
            for (int j = 0; j < 4; j++)
                mma16816(sacc[j], aql[kc][0], aql[kc][1], aql[kc][2], aql[kc][3], kh0[j], kh1[j]);
        }

        // --- online softmax ---
        float r0 = -1e30f, r1 = -1e30f;
#pragma unroll
        for (int j = 0; j < 4; j++) {
            r0 = fmaxf(r0, fmaxf(sacc[j][0], sacc[j][1]));
            r1 = fmaxf(r1, fmaxf(sacc[j][2], sacc[j][3]));
        }
        r0 = fmaxf(r0, __shfl_xor_sync(0xFFFFFFFFu, r0, 1));
        r0 = fmaxf(r0, __shfl_xor_sync(0xFFFFFFFFu, r0, 2));
        r1 = fmaxf(r1, __shfl_xor_sync(0xFFFFFFFFu, r1, 1));
        r1 = fmaxf(r1, __shfl_xor_sync(0xFFFFFFFFu, r1, 2));
        float mn0 = fmaxf(m0, r0), mn1 = fmaxf(m1, r1);
        float corr0 = __expf(m0 - mn0), corr1 = __expf(m1 - mn1);
        m0 = mn0; m1 = mn1;

        float ls0 = 0.f, ls1 = 0.f;
#pragma unroll
        for (int j = 0; j < 4; j++) {
            sacc[j][0] = __expf(sacc[j][0] - mn0);
            sacc[j][1] = __expf(sacc[j][1] - mn0);
            sacc[j][2] = __expf(sacc[j][2] - mn1);
            sacc[j][3] = __expf(sacc[j][3] - mn1);
            ls0 += sacc[j][0] + sacc[j][1];
            ls1 += sacc[j][2] + sacc[j][3];
        }
        ls0 += __shfl_xor_sync(0xFFFFFFFFu, ls0, 1);
        ls0 += __shfl_xor_sync(0xFFFFFFFFu, ls0, 2);
        ls1 += __shfl_xor_sync(0xFFFFFFFFu, ls1, 1);
        ls1 += __shfl_xor_sync(0xFFFFFFFFu, ls1, 2);
        l0 = l0 * corr0 + ls0;
        l1 = l1 * corr1 + ls1;

#pragma unroll
        for (int dt = 0; dt < 8; dt++) {
            oacc[dt][0] *= corr0; oacc[dt][1] *= corr0;
            oacc[dt][2] *= corr1; oacc[dt][3] *= corr1;
        }

        // --- P fragments (C layout == A layout), bf16 hi/lo ---
        unsigned aph[2][4], apl[2][4];
#pragma unroll
        for (int kc2 = 0; kc2 < 2; kc2++) {
            int j0 = 2 * kc2, j1 = 2 * kc2 + 1;
            bsplit2(sacc[j0][0], sacc[j0][1], aph[kc2][0], apl[kc2][0]);
            bsplit2(sacc[j0][2], sacc[j0][3], aph[kc2][1], apl[kc2][1]);
            bsplit2(sacc[j1][0], sacc[j1][1], aph[kc2][2], apl[kc2][2]);
            bsplit2(sacc[j1][2], sacc[j1][3], aph[kc2][3], apl[kc2][3]);
        }

        // --- PV: kc2-outer, V-frag hoist, term-outer over dt (dist 8) ---
#pragma unroll
        for (int kc2 = 0; kc2 < 2; kc2++) {
            const int k0c = 16 * kc2 + 2 * tig;
            unsigned vh0[8], vh1[8], vl0[8], vl1[8];
#pragma unroll
            for (int dt = 0; dt < 8; dt++) {
                int drow = 8 * dt + g;
                vh0[dt] = *(const unsigned*)&Vsh[p][drow][k0c];
                vh1[dt] = *(const unsigned*)&Vsh[p][drow][k0c + 8];
                vl0[dt] = *(const unsigned*)&Vsl[p][drow][k0c];
                vl1[dt] = *(const unsigned*)&Vsl[p][drow][k0c + 8];
            }
#pragma unroll
            for (int dt = 0; dt < 8; dt++)
                mma16816(oacc[dt], aph[kc2][0], aph[kc2][1], aph[kc2][2], aph[kc2][3], vh0[dt], vh1[dt]);
#pragma unroll
            for (int dt = 0; dt < 8; dt++)
                mma16816(oacc[dt], aph[kc2][0], aph[kc2][1], aph[kc2][2], aph[kc2][3], vl0[dt], vl1[dt]);
#pragma unroll
            for (int dt = 0; dt < 8; dt++)
                mma16816(oacc[dt], apl[kc2][0], apl[kc2][1], apl[kc2][2], apl[kc2][3], vh0[dt], vh1[dt]);
        }
        __syncthreads();
        p ^= 1;
    }

    const int b_ = bh >> 4, h = bh & 15;
    const float inv0 = 1.f / l0, inv1 = 1.f / l1;
    const int qg0 = qbase + g, qg1 = qbase + g + 8;
    const size_t o0 = ((size_t)(b_ * SEQ + qg0)) * DIM + h * HD;
    const size_t o1 = ((size_t)(b_ * SEQ + qg1)) * DIM + h * HD;
#pragma unroll
    for (int dt = 0; dt < 8; dt++) {
        int d = 8 * dt + 2 * tig;
        __nv_bfloat162 hh, ll;
        bsplit2v(oacc[dt][0] * inv0, oacc[dt][1] * inv0, hh, ll);
        *(__nv_bfloat162*)&g_Ah[o0 + d] = hh;
        *(__nv_bfloat162*)&g_Al[o0 + d] = ll;
        bsplit2v(oacc[dt][2] * inv1, oacc[dt][3] * inv1, hh, ll);
        *(__nv_bfloat162*)&g_Ah[o1 + d] = hh;
        *(__nv_bfloat162*)&g_Al[o1 + d] = ll;
    }
}

// ---------------- GEMM 2: out = attn @ w_out + b_out ----------------------
__global__ __launch_bounds__(128) void gemm_out_mma(const float* __restrict__ bias,
                                                    float* __restrict__ out)
{
    float acc[4][8][4];
#pragma unroll
    for (int mt = 0; mt < 4; mt++)
#pragma unroll
        for (int nt = 0; nt < 8; nt++)
#pragma unroll
            for (int e = 0; e < 4; e++) acc[mt][nt][e] = 0.f;

    const int row0 = blockIdx.y * 128, col0 = blockIdx.x * 128;
    gemm_core(g_Ah, g_Al, g_woh, g_wol, DIM, row0, col0, acc);

    const int lane = threadIdx.x & 31, warp = threadIdx.x >> 5;
    const int g = lane >> 2, tig = lane & 3;
    const int wm = (warp & 1) * 64, wn = (warp >> 1) * 64;

#pragma unroll
    for (int nt = 0; nt < 8; nt++) {
        int cb = col0 + wn + nt * 8 + 2 * tig;
        float bv0 = bias[cb], bv1 = bias[cb + 1];
#pragma unroll
        for (int mt = 0; mt < 4; mt++) {
            int r = row0 + wm + mt * 16 + g;
            *(float2*)&out[(size_t)r * DIM + cb] =
                make_float2(acc[mt][nt][0] + bv0, acc[mt][nt][1] + bv1);
            *(float2*)&out[(size_t)(r + 8) * DIM + cb] =
                make_float2(acc[mt][nt][2] + bv0, acc[mt][nt][3] + bv1);
        }
    }
}

extern "C" void kernel_launch(void* const* d_in, const int* in_sizes, int n_in,
                              void* d_out, int out_size)
{
    (void)in_sizes; (void)n_in; (void)out_size;
    const float* x     = (const float*)d_in[0];
    const float* w_qkv = (const float*)d_in[1];
    const float* b_qkv = (const float*)d_in[2];
    const float* w_out = (const float*)d_in[3];
    const float* b_out = (const float*)d_in[4];
    float* out = (float*)d_out;

    const int GEMM_SMEM = 2 * 4 * GST * (int)sizeof(__nv_bfloat16);  // 81920
    cudaFuncSetAttribute(gemm_qkv_mma,
                         cudaFuncAttributeMaxDynamicSharedMemorySize, GEMM_SMEM);
    cudaFuncSetAttribute(gemm_out_mma,
                         cudaFuncAttributeMaxDynamicSharedMemorySize, GEMM_SMEM);

    split_x<<<MROWS * DIM / 1024, 256>>>(x);
    tsplit_w<<<dim3(QKV_N / 32, DIM / 32), 256>>>(w_qkv, QKV_N, 0);
    tsplit_w<<<dim3(DIM / 32, DIM / 32), 256>>>(w_out, DIM, 1);
    gemm_qkv_mma<<<dim3(QKV_N / 128, MROWS / 128), 128, GEMM_SMEM>>>(b_qkv);
    convert_v<<<dim3(SEQ / 64, BH), 256>>>();
    attn_mma<<<dim3(SEQ / 64, BH), 128>>>();
    gemm_out_mma<<<dim3(DIM / 128, MROWS / 128), 128, GEMM_SMEM>>>(b_out, out);
}